// round 10
// baseline (speedup 1.0000x reference)
#include <cuda_runtime.h>
#include <cuda_bf16.h>
#include <math.h>
#include <stdint.h>

// ---------------------------------------------------------------------------
// Problem constants
// ---------------------------------------------------------------------------
namespace {
constexpr int B_ = 128, L_ = 128, D_ = 6, FD_ = 256;
constexpr int IN_ATOM_ = 39, IN_BOND_ = 10, NBONDS_ = 256;
constexpr int RADIUS_ = 3, TASKS_ = 4, T_ = 2;
constexpr int BL_ = B_ * L_;        // 16384
constexpr int BLD_ = BL_ * D_;      // 98304
constexpr float NEG_ = -9e8f;
constexpr int GN_ = 3 * FD_;        // 768
}

// ---------------------------------------------------------------------------
// Scratch buffers (device globals; no allocations allowed)
// ---------------------------------------------------------------------------
__device__ float g_atomfeat[BL_ * FD_];
__device__ float g_nbrfeat [BLD_ * FD_];
__device__ float g_h       [BL_ * FD_];
__device__ float g_act     [BL_ * FD_];
__device__ float g_actT    [BL_ * FD_];
__device__ float g_gi      [BL_ * GN_];
__device__ float g_gh      [BL_ * GN_];
__device__ float g_nbrdot0 [BLD_];
__device__ float g_sd      [BL_];
__device__ float g_nd      [BL_];
__device__ float g_wsum    [BL_];
__device__ float g_actdot  [TASKS_ * BL_];
__device__ float g_molfeat [B_ * FD_];
__device__ float g_actmol  [B_ * FD_];
__device__ float g_mgi     [B_ * GN_];
__device__ float g_mgh     [B_ * GN_];

// bf16 hi/lo activation buffers (16B aligned for uint4 / cp.async staging)
__device__ __align__(16) __nv_bfloat16 g_af_h [BL_ * FD_];
__device__ __align__(16) __nv_bfloat16 g_af_l [BL_ * FD_];
__device__ __align__(16) __nv_bfloat16 g_wf_h [BL_ * FD_];
__device__ __align__(16) __nv_bfloat16 g_wf_l [BL_ * FD_];
__device__ __align__(16) __nv_bfloat16 g_ctx_h[BL_ * FD_];
__device__ __align__(16) __nv_bfloat16 g_ctx_l[BL_ * FD_];
__device__ __align__(16) __nv_bfloat16 g_h_h  [BL_ * FD_];
__device__ __align__(16) __nv_bfloat16 g_h_l  [BL_ * FD_];
__device__ __align__(16) __nv_bfloat16 g_act_h[BL_ * FD_];
__device__ __align__(16) __nv_bfloat16 g_act_l[BL_ * FD_];
__device__ __align__(16) __nv_bfloat16 g_mctx_h[B_ * FD_];
__device__ __align__(16) __nv_bfloat16 g_mctx_l[B_ * FD_];
__device__ __align__(16) __nv_bfloat16 g_mf_h [B_ * FD_];
__device__ __align__(16) __nv_bfloat16 g_mf_l [B_ * FD_];
// bf16 hi/lo weights
__device__ __align__(16) __nv_bfloat16 g_watt_h[RADIUS_ * FD_ * FD_];
__device__ __align__(16) __nv_bfloat16 g_watt_l[RADIUS_ * FD_ * FD_];
__device__ __align__(16) __nv_bfloat16 g_wih_h [RADIUS_ * GN_ * FD_];
__device__ __align__(16) __nv_bfloat16 g_wih_l [RADIUS_ * GN_ * FD_];
__device__ __align__(16) __nv_bfloat16 g_whh_h [RADIUS_ * GN_ * FD_];
__device__ __align__(16) __nv_bfloat16 g_whh_l [RADIUS_ * GN_ * FD_];
__device__ __align__(16) __nv_bfloat16 g_mat_h [FD_ * FD_];
__device__ __align__(16) __nv_bfloat16 g_mat_l [FD_ * FD_];
__device__ __align__(16) __nv_bfloat16 g_mih_h [GN_ * FD_];
__device__ __align__(16) __nv_bfloat16 g_mih_l [GN_ * FD_];
__device__ __align__(16) __nv_bfloat16 g_mhh_h [GN_ * FD_];
__device__ __align__(16) __nv_bfloat16 g_mhh_l [GN_ * FD_];

__device__ __forceinline__ float lrelu_(float x) { return x > 0.f ? x : 0.01f * x; }
__device__ __forceinline__ float elu_(float x)   { return x > 0.f ? x : expm1f(x); }
__device__ __forceinline__ float sigm_(float x)  { return 1.f / (1.f + expf(-x)); }

__device__ __forceinline__ void split_bf16(float v, __nv_bfloat16* hp, __nv_bfloat16* lp) {
    __nv_bfloat16 h = __float2bfloat16(v);
    *hp = h;
    *lp = __float2bfloat16(v - __bfloat162float(h));
}

// ---------------------------------------------------------------------------
// mma.sync + ldmatrix + cp.async helpers (baseline PTX, compute_103-safe)
// ---------------------------------------------------------------------------
__device__ __forceinline__ uint32_t smem_u32_(const void* p) {
    uint32_t a;
    asm("{ .reg .u64 t; cvta.to.shared.u64 t, %1; cvt.u32.u64 %0, t; }" : "=r"(a) : "l"(p));
    return a;
}
__device__ __forceinline__ void ldm_x4_(uint32_t* r, uint32_t addr) {
    asm volatile("ldmatrix.sync.aligned.m8n8.x4.shared.b16 {%0,%1,%2,%3}, [%4];"
                 : "=r"(r[0]), "=r"(r[1]), "=r"(r[2]), "=r"(r[3]) : "r"(addr));
}
__device__ __forceinline__ void mma_(float* d, const uint32_t* a, uint32_t b0, uint32_t b1) {
    asm volatile(
        "mma.sync.aligned.m16n8k16.row.col.f32.bf16.bf16.f32 "
        "{%0,%1,%2,%3}, {%4,%5,%6,%7}, {%8,%9}, {%0,%1,%2,%3};"
        : "+f"(d[0]), "+f"(d[1]), "+f"(d[2]), "+f"(d[3])
        : "r"(a[0]), "r"(a[1]), "r"(a[2]), "r"(a[3]), "r"(b0), "r"(b1));
}
__device__ __forceinline__ void cp16_(uint32_t dst, const void* src) {
    asm volatile("cp.async.cg.shared.global [%0], [%1], 16;" :: "r"(dst), "l"(src));
}

// ---------------------------------------------------------------------------
// Pipelined HMMA GEMM with register-level fragment double buffering.
// C = (Ahi+Alo)[M,256] @ (Whi+Wlo)[N,256]^T (bf16x3 emulation)
// CTA: 128 thr / 4 warps (2x2), tile 128x64, warp tile 64x32.
// K chunks of 64, 2-stage cp.async smem pipeline + 2-deep frag pipeline.
// EPI 0: Cf = acc + bias[n]  (fp32)
// EPI 2: elu(acc + rs[m]*bias[n]) -> Chi/Clo bf16 split
// gridDim.z==2 selects second (A2/W2/bias2/C2f) problem.
// ---------------------------------------------------------------------------
namespace {
constexpr int SMS_ = 72;                       // bf16 row stride (144 B)
constexpr int ST_AH = 0;
constexpr int ST_AL = 128 * SMS_ * 2;          // 18432
constexpr int ST_WH = 2 * 128 * SMS_ * 2;      // 36864
constexpr int ST_WL = ST_WH + 64 * SMS_ * 2;   // 46080
constexpr int STAGE_ = ST_WL + 64 * SMS_ * 2;  // 55296
constexpr int SM_TOTAL = 2 * STAGE_;           // 110592
}

template <int EPI>
__global__ __launch_bounds__(128)
void tgemm(const __nv_bfloat16* __restrict__ Ahi, const __nv_bfloat16* __restrict__ Alo,
           const __nv_bfloat16* __restrict__ A2hi, const __nv_bfloat16* __restrict__ A2lo,
           const __nv_bfloat16* __restrict__ Whi, const __nv_bfloat16* __restrict__ Wlo,
           const __nv_bfloat16* __restrict__ W2hi, const __nv_bfloat16* __restrict__ W2lo,
           const float* __restrict__ bias, const float* __restrict__ bias2,
           const float* __restrict__ rs,
           float* __restrict__ Cf, float* __restrict__ C2f,
           __nv_bfloat16* __restrict__ Chi, __nv_bfloat16* __restrict__ Clo,
           int N)
{
    extern __shared__ char sm[];
    const uint32_t smb = smem_u32_(sm);
    const int tid = threadIdx.x, wid = tid >> 5, lane = tid & 31;
    if (blockIdx.z) { Ahi = A2hi; Alo = A2lo; Whi = W2hi; Wlo = W2lo; bias = bias2; Cf = C2f; }
    const int bm = blockIdx.y * 128, bn = blockIdx.x * 64;
    constexpr int K = 256;
    const int warp_m = wid >> 1, warp_n = wid & 1;

    auto stage = [&](int kc, int s) {
        const int koff = kc * 64;
        const uint32_t base = smb + s * STAGE_;
        for (int i = tid; i < 1024; i += 128) {          // A: 128 rows x 4x16B
            int r = i >> 3, cb = (i & 7) << 4;
            uint32_t dst = (uint32_t)(r * 144 + cb);
            size_t g = (size_t)(bm + r) * K + koff + (cb >> 1);
            cp16_(base + ST_AH + dst, Ahi + g);
            cp16_(base + ST_AL + dst, Alo + g);
        }
        for (int i = tid; i < 512; i += 128) {           // W: 64 rows
            int r = i >> 3, cb = (i & 7) << 4;
            uint32_t dst = (uint32_t)(r * 144 + cb);
            size_t g = (size_t)(bn + r) * K + koff + (cb >> 1);
            cp16_(base + ST_WH + dst, Whi + g);
            cp16_(base + ST_WL + dst, Wlo + g);
        }
        asm volatile("cp.async.commit_group;");
    };

    stage(0, 0);
    stage(1, 1);

    float acc[4][4][4] = {};
    const int lrow = lane & 15;
    const int lcol = (lane >> 4) << 3;
    const uint32_t a_base_off = (uint32_t)((warp_m * 64 + lrow) * SMS_ + lcol) * 2;
    const uint32_t b_base_off = (uint32_t)((warp_n * 32 + lrow) * SMS_ + lcol) * 2;

    // register fragment double buffer
    uint32_t ah[2][4][4], al[2][4][4], bh[2][2][4], bl[2][2][4];

    auto load_frags = [&](uint32_t sb, int ks, int buf) {
        const uint32_t ko = (uint32_t)(ks * 16) * 2;
#pragma unroll
        for (int i = 0; i < 4; i++) {
            uint32_t off = a_base_off + (uint32_t)(i * 16 * SMS_) * 2 + ko;
            ldm_x4_(ah[buf][i], sb + ST_AH + off);
            ldm_x4_(al[buf][i], sb + ST_AL + off);
        }
#pragma unroll
        for (int j2 = 0; j2 < 2; j2++) {
            uint32_t off = b_base_off + (uint32_t)(j2 * 16 * SMS_) * 2 + ko;
            ldm_x4_(bh[buf][j2], sb + ST_WH + off);
            ldm_x4_(bl[buf][j2], sb + ST_WL + off);
        }
    };

#pragma unroll
    for (int kc = 0; kc < 4; kc++) {
        if (kc == 3) asm volatile("cp.async.wait_group 0;");
        else         asm volatile("cp.async.wait_group 1;");
        __syncthreads();
        const uint32_t sb = smb + (kc & 1) * STAGE_;
        load_frags(sb, 0, 0);
#pragma unroll
        for (int ks = 0; ks < 4; ks++) {
            const int cur = ks & 1;
            if (ks < 3) load_frags(sb, ks + 1, cur ^ 1);
#pragma unroll
            for (int i = 0; i < 4; i++) {
#pragma unroll
                for (int j2 = 0; j2 < 2; j2++) {
#pragma unroll
                    for (int s = 0; s < 2; s++) {
                        float* d = acc[i][j2 * 2 + s];
                        mma_(d, ah[cur][i], bh[cur][j2][s], bh[cur][j2][s + 2]);   // hi*hi
                        mma_(d, ah[cur][i], bl[cur][j2][s], bl[cur][j2][s + 2]);   // hi*lo
                        mma_(d, al[cur][i], bh[cur][j2][s], bh[cur][j2][s + 2]);   // lo*hi
                    }
                }
            }
        }
        if (kc < 2) {
            __syncthreads();
            stage(kc + 2, kc & 1);
        }
    }

    const int er = lane >> 2, ec = (lane & 3) << 1;
#pragma unroll
    for (int i = 0; i < 4; i++) {
        int m0 = bm + warp_m * 64 + i * 16 + er;
#pragma unroll
        for (int j = 0; j < 4; j++) {
            int n0 = bn + warp_n * 32 + j * 8 + ec;
            float b0 = bias[n0], b1 = bias[n0 + 1];
            if (EPI == 0) {
#pragma unroll
                for (int h = 0; h < 2; h++) {
                    int m = m0 + h * 8;
                    float2 o;
                    o.x = acc[i][j][2 * h + 0] + b0;
                    o.y = acc[i][j][2 * h + 1] + b1;
                    *(float2*)(Cf + (size_t)m * N + n0) = o;
                }
            } else {
#pragma unroll
                for (int h = 0; h < 2; h++) {
                    int m = m0 + h * 8;
                    float rsv = rs[m];
                    float v0 = elu_(acc[i][j][2 * h + 0] + rsv * b0);
                    float v1 = elu_(acc[i][j][2 * h + 1] + rsv * b1);
                    __nv_bfloat16 h0, l0, h1, l1;
                    split_bf16(v0, &h0, &l0); split_bf16(v1, &h1, &l1);
                    *(__nv_bfloat162*)(Chi + (size_t)m * N + n0) = __nv_bfloat162{h0, h1};
                    *(__nv_bfloat162*)(Clo + (size_t)m * N + n0) = __nv_bfloat162{l0, l1};
                }
            }
        }
    }
}

// ---------------------------------------------------------------------------
// fp32 -> bf16 hi/lo conversion: ALL weights in one launch
// ---------------------------------------------------------------------------
namespace {
constexpr int CV1 = RADIUS_ * FD_ * FD_;
constexpr int CV2 = CV1 + RADIUS_ * GN_ * FD_;
constexpr int CV3 = CV2 + RADIUS_ * GN_ * FD_;
constexpr int CV4 = CV3 + FD_ * FD_;
constexpr int CV5 = CV4 + GN_ * FD_;
constexpr int CV6 = CV5 + GN_ * FD_;
}
__global__ void fp_cvt_all(const float* __restrict__ s1, const float* __restrict__ s2,
                           const float* __restrict__ s3, const float* __restrict__ s4,
                           const float* __restrict__ s5, const float* __restrict__ s6,
                           __nv_bfloat16* __restrict__ h1, __nv_bfloat16* __restrict__ l1,
                           __nv_bfloat16* __restrict__ h2, __nv_bfloat16* __restrict__ l2,
                           __nv_bfloat16* __restrict__ h3, __nv_bfloat16* __restrict__ l3,
                           __nv_bfloat16* __restrict__ h4, __nv_bfloat16* __restrict__ l4,
                           __nv_bfloat16* __restrict__ h5, __nv_bfloat16* __restrict__ l5,
                           __nv_bfloat16* __restrict__ h6, __nv_bfloat16* __restrict__ l6)
{
    int i = blockIdx.x * 256 + threadIdx.x;
    if (i >= CV6) return;
    const float* s; __nv_bfloat16 *h, *l; int o;
    if      (i < CV1) { s = s1; h = h1; l = l1; o = 0;   }
    else if (i < CV2) { s = s2; h = h2; l = l2; o = CV1; }
    else if (i < CV3) { s = s3; h = h3; l = l3; o = CV2; }
    else if (i < CV4) { s = s4; h = h4; l = l4; o = CV3; }
    else if (i < CV5) { s = s5; h = h5; l = l5; o = CV4; }
    else              { s = s6; h = h6; l = l6; o = CV5; }
    int j = i - o;
    split_bf16(s[j], h + j, l + j);
}

// ---------------------------------------------------------------------------
// atom_fc: lrelu(X @ W^T + b); fp32 + bf16 hi/lo + fused self-dot (align_w[0])
// ---------------------------------------------------------------------------
__global__ __launch_bounds__(256)
void fp_atom_fc(const float* __restrict__ X, const float* __restrict__ W,
                const float* __restrict__ bias, const float* __restrict__ vdot,
                float* __restrict__ C,
                __nv_bfloat16* __restrict__ Ch, __nv_bfloat16* __restrict__ Cl,
                float* __restrict__ sd)
{
    __shared__ float sin_[16][IN_ATOM_];
    __shared__ float sred[16][8];
    const int r0 = blockIdx.x * 16;
    for (int i = threadIdx.x; i < 16 * IN_ATOM_; i += 256)
        sin_[i / IN_ATOM_][i % IN_ATOM_] =
            X[(size_t)(r0 + i / IN_ATOM_) * IN_ATOM_ + i % IN_ATOM_];
    __syncthreads();
    const int f = threadIdx.x;
    float acc[16] = {};
    for (int k = 0; k < IN_ATOM_; k++) {
        float wv = __ldg(&W[f * IN_ATOM_ + k]);
#pragma unroll
        for (int r = 0; r < 16; r++) acc[r] += wv * sin_[r][k];
    }
    float bv = bias[f];
    float vw = __ldg(&vdot[f]);
    const int lw = threadIdx.x >> 5, ll = threadIdx.x & 31;
#pragma unroll
    for (int r = 0; r < 16; r++) {
        float v = lrelu_(acc[r] + bv);
        size_t o = (size_t)(r0 + r) * FD_ + f;
        C[o] = v;
        split_bf16(v, Ch + o, Cl + o);
        float p = v * vw;
#pragma unroll
        for (int oo = 16; oo; oo >>= 1) p += __shfl_down_sync(0xffffffffu, p, oo);
        if (ll == 0) sred[r][lw] = p;
    }
    __syncthreads();
    if (threadIdx.x < 16) {
        float s = 0.f;
#pragma unroll
        for (int wdx = 0; wdx < 8; wdx++) s += sred[threadIdx.x][wdx];
        sd[r0 + threadIdx.x] = s;
    }
}

// ---------------------------------------------------------------------------
// neighbor_fc + fused rowdot vs align_w nbr-half (writes nbrdot0 directly)
// ---------------------------------------------------------------------------
__global__ __launch_bounds__(256)
void fp_neighbor_fc(const float* __restrict__ atom_list, const float* __restrict__ bond_list,
                    const int* __restrict__ adeg, const int* __restrict__ bdeg,
                    const float* __restrict__ W, const float* __restrict__ bias,
                    const float* __restrict__ vdot, float* __restrict__ C,
                    float* __restrict__ nd0)
{
    constexpr int KIN = IN_ATOM_ + IN_BOND_;
    __shared__ float sin_[16][KIN];
    __shared__ float sred[16][8];
    const int r0 = blockIdx.x * 16;
    for (int i = threadIdx.x; i < 16 * KIN; i += 256) {
        int r = i / KIN, k = i % KIN;
        int rid = r0 + r;
        int bb = rid / (L_ * D_);
        float v;
        if (k < IN_ATOM_) v = atom_list[((size_t)bb * L_ + adeg[rid]) * IN_ATOM_ + k];
        else              v = bond_list[((size_t)bb * NBONDS_ + bdeg[rid]) * IN_BOND_ + (k - IN_ATOM_)];
        sin_[r][k] = v;
    }
    __syncthreads();
    const int f = threadIdx.x;
    float acc[16] = {};
    for (int k = 0; k < KIN; k++) {
        float wv = __ldg(&W[f * KIN + k]);
#pragma unroll
        for (int r = 0; r < 16; r++) acc[r] += wv * sin_[r][k];
    }
    float bv = bias[f];
    float vw = __ldg(&vdot[f]);
    const int lw = threadIdx.x >> 5, ll = threadIdx.x & 31;
#pragma unroll
    for (int r = 0; r < 16; r++) {
        float v = lrelu_(acc[r] + bv);
        C[(size_t)(r0 + r) * FD_ + f] = v;
        float p = v * vw;
#pragma unroll
        for (int o = 16; o; o >>= 1) p += __shfl_down_sync(0xffffffffu, p, o);
        if (ll == 0) sred[r][lw] = p;
    }
    __syncthreads();
    if (threadIdx.x < 16) {
        float s = 0.f;
#pragma unroll
        for (int wdx = 0; wdx < 8; wdx++) s += sred[threadIdx.x][wdx];
        nd0[r0 + threadIdx.x] = s;
    }
}

// ---------------------------------------------------------------------------
// FUSED attention: score + softmax over D=6 + weighted neighbor sum.
// Block handles 2 atoms; threads 0 / 128 compute the softmax serially.
// Writes wf bf16 hi/lo and wsum (for the ctx GEMM epilogue).
// ---------------------------------------------------------------------------
template <int FIRST>
__global__ __launch_bounds__(256)
void fp_attn(const float* __restrict__ sd, const float* __restrict__ nd,
             const int* __restrict__ adeg, const float* __restrict__ ab_ptr,
             const float* __restrict__ src,
             __nv_bfloat16* __restrict__ wfh, __nv_bfloat16* __restrict__ wfl,
             float* __restrict__ wsum)
{
    __shared__ float sw[2][D_];
    __shared__ int sidx[2][D_];
    const int m0 = blockIdx.x * 2;

    if ((threadIdx.x & 127) == 0) {
        const int r = threadIdx.x >> 7;
        const int m = m0 + r;
        const int b = m / L_;
        const float ab = ab_ptr[0];
        const float sdv = sd[m];
        float sc[D_], msk[D_];
        int idxs[D_];
        float mx = -3.4e38f;
#pragma unroll
        for (int d = 0; d < D_; d++) {
            int idx = adeg[m * D_ + d];
            idxs[d] = idx;
            float ndv = FIRST ? nd[m * D_ + d] : nd[b * L_ + idx];
            float s = lrelu_(sdv + ndv + ab);
            bool pad = (idx == L_ - 1);
            if (pad) s += NEG_;
            msk[d] = pad ? 0.f : 1.f;
            sc[d] = s;
            mx = fmaxf(mx, s);
        }
        float sum = 0.f;
#pragma unroll
        for (int d = 0; d < D_; d++) { float e = expf(sc[d] - mx); sum += e; sc[d] = e; }
        float inv = 1.f / sum, ws = 0.f;
#pragma unroll
        for (int d = 0; d < D_; d++) {
            float wv = sc[d] * inv * msk[d];
            sw[r][d] = wv;
            sidx[r][d] = idxs[d];
            ws += wv;
        }
        wsum[m] = ws;
    }
    __syncthreads();

    const int f = threadIdx.x;
#pragma unroll
    for (int r = 0; r < 2; r++) {
        int m = m0 + r;
        int b = m / L_;
        float acc = 0.f;
#pragma unroll
        for (int d = 0; d < D_; d++) {
            float xv = FIRST ? src[((size_t)m * D_ + d) * FD_ + f]
                             : src[(size_t)(b * L_ + sidx[r][d]) * FD_ + f];
            acc += sw[r][d] * xv;
        }
        split_bf16(acc, wfh + (size_t)m * FD_ + f, wfl + (size_t)m * FD_ + f);
    }
}

// ---------------------------------------------------------------------------
// GRU gate + fused dot products on act (one block per row, 256 threads).
// ---------------------------------------------------------------------------
__global__ __launch_bounds__(256)
void fp_gru_gate_dot(const float* __restrict__ gi, const float* __restrict__ gh,
                     const float* __restrict__ hin, float* __restrict__ hout,
                     __nv_bfloat16* __restrict__ hh, __nv_bfloat16* __restrict__ hl,
                     float* __restrict__ act,
                     __nv_bfloat16* __restrict__ ah, __nv_bfloat16* __restrict__ al,
                     const float* __restrict__ v0, const float* __restrict__ v1,
                     const float* __restrict__ v2, const float* __restrict__ v3,
                     float* __restrict__ y0, float* __restrict__ y1,
                     float* __restrict__ y2, float* __restrict__ y3)
{
    __shared__ float sred[4][8];
    const int m = blockIdx.x, f = threadIdx.x;
    const size_t g = (size_t)m * FD_ + f;
    const float* gim = gi + (size_t)m * GN_;
    const float* ghm = gh + (size_t)m * GN_;
    float r = sigm_(gim[f] + ghm[f]);
    float z = sigm_(gim[FD_ + f] + ghm[FD_ + f]);
    float n = tanhf(gim[2 * FD_ + f] + r * ghm[2 * FD_ + f]);
    float h = (1.f - z) * n + z * hin[g];
    hout[g] = h;
    if (hh) split_bf16(h, hh + g, hl + g);
    float a = fmaxf(h, 0.f);
    act[g] = a;
    if (ah) split_bf16(a, ah + g, al + g);

    float p0 = a * v0[f];
    float p1 = a * v1[f];
    float p2 = v2 ? a * v2[f] : 0.f;
    float p3 = v3 ? a * v3[f] : 0.f;
#pragma unroll
    for (int o = 16; o; o >>= 1) {
        p0 += __shfl_down_sync(0xffffffffu, p0, o);
        p1 += __shfl_down_sync(0xffffffffu, p1, o);
        p2 += __shfl_down_sync(0xffffffffu, p2, o);
        p3 += __shfl_down_sync(0xffffffffu, p3, o);
    }
    const int lw = f >> 5, ll = f & 31;
    if (ll == 0) { sred[0][lw] = p0; sred[1][lw] = p1; sred[2][lw] = p2; sred[3][lw] = p3; }
    __syncthreads();
    if (f < 4) {
        float s = 0.f;
#pragma unroll
        for (int wdx = 0; wdx < 8; wdx++) s += sred[f][wdx];
        if      (f == 0) y0[m] = s;
        else if (f == 1) y1[m] = s;
        else if (f == 2) { if (y2) y2[m] = s; }
        else             { if (y3) y3[m] = s; }
    }
}

// ---------------------------------------------------------------------------
// Flat GRU gate (final mol step)
// ---------------------------------------------------------------------------
__global__ void fp_gru_gate(const float* __restrict__ gi, const float* __restrict__ gh,
                            const float* __restrict__ hin, float* __restrict__ hout,
                            float* __restrict__ out, int M)
{
    int g = blockIdx.x * blockDim.x + threadIdx.x;
    if (g >= M * FD_) return;
    int m = g / FD_, f = g - m * FD_;
    const float* gim = gi + (size_t)m * GN_;
    const float* ghm = gh + (size_t)m * GN_;
    float r = sigm_(gim[f] + ghm[f]);
    float z = sigm_(gim[FD_ + f] + ghm[FD_ + f]);
    float n = tanhf(gim[2 * FD_ + f] + r * ghm[2 * FD_ + f]);
    float h = (1.f - z) * n + z * hin[g];
    hout[g] = h;
    out[g] = fmaxf(h, 0.f);
}

// ---------------------------------------------------------------------------
// molecule feature init
// ---------------------------------------------------------------------------
__global__ void fp_molfeat(const float* __restrict__ act, const float* __restrict__ amask,
                           float* __restrict__ mf, __nv_bfloat16* __restrict__ mfh,
                           __nv_bfloat16* __restrict__ mfl, float* __restrict__ am)
{
    int b = blockIdx.x, f = threadIdx.x;
    float acc = 0.f;
    for (int l = 0; l < L_; l++)
        acc += act[((size_t)b * L_ + l) * FD_ + f] * amask[b * L_ + l];
    mf[b * FD_ + f] = acc;
    split_bf16(acc, mfh + b * FD_ + f, mfl + b * FD_ + f);
    am[b * FD_ + f] = fmaxf(acc, 0.f);
}

// ---------------------------------------------------------------------------
// Fused (optional GRU gate) + mol score + softmax + context, per-molecule.
// ---------------------------------------------------------------------------
__global__ __launch_bounds__(128)
void fp_molstep(const float* __restrict__ gi, const float* __restrict__ gh,
                float* __restrict__ mf, __nv_bfloat16* __restrict__ mfh,
                __nv_bfloat16* __restrict__ mfl, const float* __restrict__ am_g,
                float* __restrict__ outp,
                const float* __restrict__ maw, const float* __restrict__ mab,
                const float* __restrict__ actdot, const float* __restrict__ amask,
                const float* __restrict__ actT,
                __nv_bfloat16* __restrict__ ctxh, __nv_bfloat16* __restrict__ ctxl, int task)
{
    __shared__ float red[128];
    __shared__ float sam[256];
    __shared__ float sw[128];
    int b = blockIdx.x, t = threadIdx.x;

    if (gi) {
        const float* gim = gi + (size_t)b * GN_;
        const float* ghm = gh + (size_t)b * GN_;
#pragma unroll
        for (int ff = 0; ff < 2; ff++) {
            int f = t + ff * 128;
            size_t g = (size_t)b * FD_ + f;
            float r = sigm_(gim[f] + ghm[f]);
            float z = sigm_(gim[FD_ + f] + ghm[FD_ + f]);
            float n = tanhf(gim[2 * FD_ + f] + r * ghm[2 * FD_ + f]);
            float h = (1.f - z) * n + z * mf[g];
            mf[g] = h;
            split_bf16(h, mfh + g, mfl + g);
            float a = fmaxf(h, 0.f);
            sam[f] = a;
            if (outp) outp[g] = a;
        }
    } else {
        sam[t] = am_g[(size_t)b * FD_ + t];
        sam[t + 128] = am_g[(size_t)b * FD_ + t + 128];
    }
    __syncthreads();

    const float* ms = maw + task * 2 * FD_;
    float p = sam[t] * ms[t] + sam[t + 128] * ms[128 + t];
    red[t] = p; __syncthreads();
    for (int st = 64; st; st >>= 1) { if (t < st) red[t] += red[t + st]; __syncthreads(); }
    float sdv = red[0]; __syncthreads();
    float amv = amask[b * L_ + t];
    float s = lrelu_(sdv + actdot[task * BL_ + b * L_ + t] + mab[task]);
    if (amv == 0.f) s += NEG_;
    red[t] = s; __syncthreads();
    for (int st = 64; st; st >>= 1) { if (t < st) red[t] = fmaxf(red[t], red[t + st]); __syncthreads(); }
    float mx = red[0]; __syncthreads();
    float e = expf(s - mx);
    red[t] = e; __syncthreads();
    for (int st = 64; st; st >>= 1) { if (t < st) red[t] += red[t + st]; __syncthreads(); }
    float sum = red[0];
    sw[t] = e / sum * amv;
    __syncthreads();
    float a0 = 0.f, a1 = 0.f;
    for (int l = 0; l < L_; l++) {
        float wv = sw[l];
        const float* row = actT + ((size_t)b * L_ + l) * FD_;
        a0 += wv * row[t];
        a1 += wv * row[t + 128];
    }
    a0 = elu_(a0); a1 = elu_(a1);
    split_bf16(a0, ctxh + b * FD_ + t, ctxl + b * FD_ + t);
    split_bf16(a1, ctxh + b * FD_ + 128 + t, ctxl + b * FD_ + 128 + t);
}

// ---------------------------------------------------------------------------
// Host launch sequence
// ---------------------------------------------------------------------------
extern "C" void kernel_launch(void* const* d_in, const int* in_sizes, int n_in,
                              void* d_out, int out_size)
{
    const float* atom_list = (const float*)d_in[0];
    const float* bond_list = (const float*)d_in[1];
    const int*   adeg      = (const int*)d_in[2];
    const int*   bdeg      = (const int*)d_in[3];
    const float* amask     = (const float*)d_in[4];
    const float* atom_fc_w = (const float*)d_in[5];
    const float* atom_fc_b = (const float*)d_in[6];
    const float* nbr_fc_w  = (const float*)d_in[7];
    const float* nbr_fc_b  = (const float*)d_in[8];
    const float* align_w   = (const float*)d_in[9];
    const float* align_b   = (const float*)d_in[10];
    const float* attend_w  = (const float*)d_in[11];
    const float* attend_b  = (const float*)d_in[12];
    const float* gru_wih   = (const float*)d_in[13];
    const float* gru_whh   = (const float*)d_in[14];
    const float* gru_bih   = (const float*)d_in[15];
    const float* gru_bhh   = (const float*)d_in[16];
    const float* mgru_wih  = (const float*)d_in[17];
    const float* mgru_whh  = (const float*)d_in[18];
    const float* mgru_bih  = (const float*)d_in[19];
    const float* mgru_bhh  = (const float*)d_in[20];
    const float* mal_w     = (const float*)d_in[21];
    const float* mal_b     = (const float*)d_in[22];
    const float* mat_w     = (const float*)d_in[23];
    const float* mat_b     = (const float*)d_in[24];
    float* out = (float*)d_out;

    cudaFuncSetAttribute((const void*)tgemm<0>, cudaFuncAttributeMaxDynamicSharedMemorySize, SM_TOTAL);
    cudaFuncSetAttribute((const void*)tgemm<2>, cudaFuncAttributeMaxDynamicSharedMemorySize, SM_TOTAL);

#define SYM(p, s) cudaGetSymbolAddress((void**)&p, s)
    float *p_af, *p_nbr, *p_h, *p_act, *p_actT, *p_gi, *p_gh, *p_nd0, *p_sd, *p_nd,
          *p_ws, *p_ad, *p_mf, *p_am, *p_mgi, *p_mgh;
    __nv_bfloat16 *p_afh, *p_afl, *p_wfh, *p_wfl, *p_cxh, *p_cxl, *p_hh, *p_hl,
                  *p_ach, *p_acl, *p_mch, *p_mcl, *p_mfh, *p_mfl,
                  *w_atth, *w_attl, *w_ihh, *w_ihl, *w_hhh, *w_hhl,
                  *w_math, *w_matl, *w_mihh, *w_mihl, *w_mhhh, *w_mhhl;
    SYM(p_af, g_atomfeat); SYM(p_nbr, g_nbrfeat); SYM(p_h, g_h); SYM(p_act, g_act);
    SYM(p_actT, g_actT); SYM(p_gi, g_gi); SYM(p_gh, g_gh); SYM(p_nd0, g_nbrdot0);
    SYM(p_sd, g_sd); SYM(p_nd, g_nd); SYM(p_ws, g_wsum);
    SYM(p_ad, g_actdot); SYM(p_mf, g_molfeat); SYM(p_am, g_actmol);
    SYM(p_mgi, g_mgi); SYM(p_mgh, g_mgh);
    SYM(p_afh, g_af_h); SYM(p_afl, g_af_l); SYM(p_wfh, g_wf_h); SYM(p_wfl, g_wf_l);
    SYM(p_cxh, g_ctx_h); SYM(p_cxl, g_ctx_l); SYM(p_hh, g_h_h); SYM(p_hl, g_h_l);
    SYM(p_ach, g_act_h); SYM(p_acl, g_act_l); SYM(p_mch, g_mctx_h); SYM(p_mcl, g_mctx_l);
    SYM(p_mfh, g_mf_h); SYM(p_mfl, g_mf_l);
    SYM(w_atth, g_watt_h); SYM(w_attl, g_watt_l); SYM(w_ihh, g_wih_h); SYM(w_ihl, g_wih_l);
    SYM(w_hhh, g_whh_h); SYM(w_hhl, g_whh_l); SYM(w_math, g_mat_h); SYM(w_matl, g_mat_l);
    SYM(w_mihh, g_mih_h); SYM(w_mihl, g_mih_l); SYM(w_mhhh, g_mhh_h); SYM(w_mhhl, g_mhh_l);
#undef SYM

    fp_cvt_all<<<(CV6 + 255) / 256, 256>>>(attend_w, gru_wih, gru_whh, mat_w, mgru_wih, mgru_whh,
                                           w_atth, w_attl, w_ihh, w_ihl, w_hhh, w_hhl,
                                           w_math, w_matl, w_mihh, w_mihl, w_mhhh, w_mhhl);

    fp_atom_fc<<<BL_ / 16, 256>>>(atom_list, atom_fc_w, atom_fc_b, align_w,
                                  p_af, p_afh, p_afl, p_sd);
    fp_neighbor_fc<<<BLD_ / 16, 256>>>(atom_list, bond_list, adeg, bdeg, nbr_fc_w, nbr_fc_b,
                                       align_w + 256, p_nbr, p_nd0);

    const dim3 gctx(FD_ / 64, BL_ / 128, 1);      // 16384 x 256
    const dim3 ggru(GN_ / 64, BL_ / 128, 2);      // 16384 x 768, batched gi/gh
    const dim3 gmol(GN_ / 64, 1, 2);              // 128 x 768, batched gi/gh

    // --- radius loop ---
    for (int r = 0; r < RADIUS_; r++) {
        const __nv_bfloat16* hprev_h = (r == 0) ? p_afh : p_hh;
        const __nv_bfloat16* hprev_l = (r == 0) ? p_afl : p_hl;
        const float* hprev_f = (r == 0) ? p_af : p_h;

        if (r == 0) {
            fp_attn<1><<<BL_ / 2, 256>>>(p_sd, p_nd0, adeg, align_b, p_nbr,
                                         p_wfh, p_wfl, p_ws);
        } else {
            fp_attn<0><<<BL_ / 2, 256>>>(p_sd, p_nd, adeg, align_b + r, p_act,
                                         p_wfh, p_wfl, p_ws);
        }
        tgemm<2><<<gctx, 128, SM_TOTAL>>>(p_wfh, p_wfl, nullptr, nullptr,
                                          w_atth + (size_t)r * FD_ * FD_, w_attl + (size_t)r * FD_ * FD_,
                                          nullptr, nullptr,
                                          attend_b + r * FD_, nullptr, p_ws,
                                          nullptr, nullptr, p_cxh, p_cxl, FD_);
        tgemm<0><<<ggru, 128, SM_TOTAL>>>(p_cxh, p_cxl, hprev_h, hprev_l,
                                          w_ihh + (size_t)r * GN_ * FD_, w_ihl + (size_t)r * GN_ * FD_,
                                          w_hhh + (size_t)r * GN_ * FD_, w_hhl + (size_t)r * GN_ * FD_,
                                          gru_bih + r * GN_, gru_bhh + r * GN_, nullptr,
                                          p_gi, p_gh, nullptr, nullptr, GN_);
        bool last = (r == RADIUS_ - 1);
        if (!last) {
            fp_gru_gate_dot<<<BL_, 256>>>(p_gi, p_gh, hprev_f, p_h, p_hh, p_hl,
                                          p_act, nullptr, nullptr,
                                          align_w + (r + 1) * 512, align_w + (r + 1) * 512 + 256,
                                          nullptr, nullptr,
                                          p_sd, p_nd, nullptr, nullptr);
        } else {
            fp_gru_gate_dot<<<BL_, 256>>>(p_gi, p_gh, hprev_f, p_h, p_hh, p_hl,
                                          p_act, p_ach, p_acl,
                                          mal_w + 256, mal_w + 512 + 256,
                                          mal_w + 1024 + 256, mal_w + 1536 + 256,
                                          p_ad, p_ad + BL_, p_ad + 2 * BL_, p_ad + 3 * BL_);
        }
    }

    // --- molecule phase ---
    fp_molfeat<<<B_, FD_>>>(p_act, amask, p_mf, p_mfh, p_mfl, p_am);
    tgemm<0><<<gctx, 128, SM_TOTAL>>>(p_ach, p_acl, nullptr, nullptr,
                                      w_math, w_matl, nullptr, nullptr,
                                      mat_b, nullptr, nullptr,
                                      p_actT, nullptr, nullptr, nullptr, FD_);

    for (int it = 0; it < TASKS_ * T_; it++) {
        int task = it >> 1;
        const float* gi_arg = (it == 0) ? nullptr : p_mgi;
        float* outp = (it > 0 && ((it - 1) & 1)) ? out + (size_t)((it - 1) >> 1) * B_ * FD_
                                                 : nullptr;
        fp_molstep<<<B_, 128>>>(gi_arg, p_mgh, p_mf, p_mfh, p_mfl, p_am, outp,
                                mal_w, mal_b, p_ad, amask, p_actT, p_mch, p_mcl, task);
        tgemm<0><<<gmol, 128, SM_TOTAL>>>(p_mch, p_mcl, p_mfh, p_mfl,
                                          w_mihh, w_mihl, w_mhhh, w_mhhl,
                                          mgru_bih, mgru_bhh, nullptr,
                                          p_mgi, p_mgh, nullptr, nullptr, GN_);
    }
    fp_gru_gate<<<B_ * FD_ / 256, 256>>>(p_mgi, p_mgh, p_mf, p_mf,
                                         out + (size_t)(TASKS_ - 1) * B_ * FD_, B_);
}

// round 11
// speedup vs baseline: 1.0479x; 1.0479x over previous
#include <cuda_runtime.h>
#include <cuda_bf16.h>
#include <math.h>
#include <stdint.h>

// ---------------------------------------------------------------------------
// Problem constants
// ---------------------------------------------------------------------------
namespace {
constexpr int B_ = 128, L_ = 128, D_ = 6, FD_ = 256;
constexpr int IN_ATOM_ = 39, IN_BOND_ = 10, NBONDS_ = 256;
constexpr int RADIUS_ = 3, TASKS_ = 4, T_ = 2;
constexpr int BL_ = B_ * L_;        // 16384
constexpr float NEG_ = -9e8f;
constexpr int GN_ = 3 * FD_;        // 768
}

// ---------------------------------------------------------------------------
// Scratch buffers (device globals; no allocations allowed)
// ---------------------------------------------------------------------------
__device__ float g_atomfeat[BL_ * FD_];
__device__ float g_h       [BL_ * FD_];
__device__ float g_act     [BL_ * FD_];
__device__ float g_actT    [BL_ * FD_];
__device__ float g_gi      [BL_ * GN_];
__device__ float g_gh      [BL_ * GN_];
__device__ float g_sd      [BL_];
__device__ float g_nd      [BL_];
__device__ float g_wsum    [BL_];
__device__ float g_actdot  [TASKS_ * BL_];
__device__ float g_molfeat [B_ * FD_];
__device__ float g_actmol  [B_ * FD_];
__device__ float g_mgi     [B_ * GN_];
__device__ float g_mgh     [B_ * GN_];

// bf16 hi/lo activation buffers (16B aligned for uint4 / cp.async staging)
__device__ __align__(16) __nv_bfloat16 g_af_h [BL_ * FD_];
__device__ __align__(16) __nv_bfloat16 g_af_l [BL_ * FD_];
__device__ __align__(16) __nv_bfloat16 g_wf_h [BL_ * FD_];
__device__ __align__(16) __nv_bfloat16 g_wf_l [BL_ * FD_];
__device__ __align__(16) __nv_bfloat16 g_ctx_h[BL_ * FD_];
__device__ __align__(16) __nv_bfloat16 g_ctx_l[BL_ * FD_];
__device__ __align__(16) __nv_bfloat16 g_h_h  [BL_ * FD_];
__device__ __align__(16) __nv_bfloat16 g_h_l  [BL_ * FD_];
__device__ __align__(16) __nv_bfloat16 g_act_h[BL_ * FD_];
__device__ __align__(16) __nv_bfloat16 g_act_l[BL_ * FD_];
__device__ __align__(16) __nv_bfloat16 g_mctx_h[B_ * FD_];
__device__ __align__(16) __nv_bfloat16 g_mctx_l[B_ * FD_];
__device__ __align__(16) __nv_bfloat16 g_mf_h [B_ * FD_];
__device__ __align__(16) __nv_bfloat16 g_mf_l [B_ * FD_];
// bf16 hi/lo weights
__device__ __align__(16) __nv_bfloat16 g_watt_h[RADIUS_ * FD_ * FD_];
__device__ __align__(16) __nv_bfloat16 g_watt_l[RADIUS_ * FD_ * FD_];
__device__ __align__(16) __nv_bfloat16 g_wih_h [RADIUS_ * GN_ * FD_];
__device__ __align__(16) __nv_bfloat16 g_wih_l [RADIUS_ * GN_ * FD_];
__device__ __align__(16) __nv_bfloat16 g_whh_h [RADIUS_ * GN_ * FD_];
__device__ __align__(16) __nv_bfloat16 g_whh_l [RADIUS_ * GN_ * FD_];
__device__ __align__(16) __nv_bfloat16 g_mat_h [FD_ * FD_];
__device__ __align__(16) __nv_bfloat16 g_mat_l [FD_ * FD_];
__device__ __align__(16) __nv_bfloat16 g_mih_h [GN_ * FD_];
__device__ __align__(16) __nv_bfloat16 g_mih_l [GN_ * FD_];
__device__ __align__(16) __nv_bfloat16 g_mhh_h [GN_ * FD_];
__device__ __align__(16) __nv_bfloat16 g_mhh_l [GN_ * FD_];

__device__ __forceinline__ float lrelu_(float x) { return x > 0.f ? x : 0.01f * x; }
__device__ __forceinline__ float elu_(float x)   { return x > 0.f ? x : expm1f(x); }
__device__ __forceinline__ float sigm_(float x)  { return 1.f / (1.f + expf(-x)); }

__device__ __forceinline__ void split_bf16(float v, __nv_bfloat16* hp, __nv_bfloat16* lp) {
    __nv_bfloat16 h = __float2bfloat16(v);
    *hp = h;
    *lp = __float2bfloat16(v - __bfloat162float(h));
}

// ---------------------------------------------------------------------------
// mma.sync + ldmatrix + cp.async helpers (baseline PTX, compute_103-safe)
// ---------------------------------------------------------------------------
__device__ __forceinline__ uint32_t smem_u32_(const void* p) {
    uint32_t a;
    asm("{ .reg .u64 t; cvta.to.shared.u64 t, %1; cvt.u32.u64 %0, t; }" : "=r"(a) : "l"(p));
    return a;
}
__device__ __forceinline__ void ldm_x4_(uint32_t* r, uint32_t addr) {
    asm volatile("ldmatrix.sync.aligned.m8n8.x4.shared.b16 {%0,%1,%2,%3}, [%4];"
                 : "=r"(r[0]), "=r"(r[1]), "=r"(r[2]), "=r"(r[3]) : "r"(addr));
}
__device__ __forceinline__ void mma_(float* d, const uint32_t* a, uint32_t b0, uint32_t b1) {
    asm volatile(
        "mma.sync.aligned.m16n8k16.row.col.f32.bf16.bf16.f32 "
        "{%0,%1,%2,%3}, {%4,%5,%6,%7}, {%8,%9}, {%0,%1,%2,%3};"
        : "+f"(d[0]), "+f"(d[1]), "+f"(d[2]), "+f"(d[3])
        : "r"(a[0]), "r"(a[1]), "r"(a[2]), "r"(a[3]), "r"(b0), "r"(b1));
}
__device__ __forceinline__ void cp16_(uint32_t dst, const void* src) {
    asm volatile("cp.async.cg.shared.global [%0], [%1], 16;" :: "r"(dst), "l"(src));
}

// ---------------------------------------------------------------------------
// Pipelined HMMA GEMM (R9 proven inner loop): C = (Ahi+Alo) @ (Whi+Wlo)^T
// CTA: 128 thr / 4 warps (2x2), tile 128x64, warp tile 64x32.
// K chunks of 64, 2-stage cp.async pipeline. smem 110,592 B -> 2 CTA/SM.
// EPI 0: Cf = acc + bias[n]  (fp32)
// EPI 2: elu(acc + rs[m]*bias[n]) -> Chi/Clo bf16 split
// gridDim.z==2 selects second (A2/W2/bias2/C2f) problem.
// ---------------------------------------------------------------------------
namespace {
constexpr int SMS_ = 72;                       // bf16 row stride (144 B)
constexpr int ST_AH = 0;
constexpr int ST_AL = 128 * SMS_ * 2;          // 18432
constexpr int ST_WH = 2 * 128 * SMS_ * 2;      // 36864
constexpr int ST_WL = ST_WH + 64 * SMS_ * 2;   // 46080
constexpr int STAGE_ = ST_WL + 64 * SMS_ * 2;  // 55296
constexpr int SM_TOTAL = 2 * STAGE_;           // 110592
}

template <int EPI>
__global__ __launch_bounds__(128)
void tgemm(const __nv_bfloat16* __restrict__ Ahi, const __nv_bfloat16* __restrict__ Alo,
           const __nv_bfloat16* __restrict__ A2hi, const __nv_bfloat16* __restrict__ A2lo,
           const __nv_bfloat16* __restrict__ Whi, const __nv_bfloat16* __restrict__ Wlo,
           const __nv_bfloat16* __restrict__ W2hi, const __nv_bfloat16* __restrict__ W2lo,
           const float* __restrict__ bias, const float* __restrict__ bias2,
           const float* __restrict__ rs,
           float* __restrict__ Cf, float* __restrict__ C2f,
           __nv_bfloat16* __restrict__ Chi, __nv_bfloat16* __restrict__ Clo,
           int N)
{
    extern __shared__ char sm[];
    const uint32_t smb = smem_u32_(sm);
    const int tid = threadIdx.x, wid = tid >> 5, lane = tid & 31;
    if (blockIdx.z) { Ahi = A2hi; Alo = A2lo; Whi = W2hi; Wlo = W2lo; bias = bias2; Cf = C2f; }
    const int bm = blockIdx.y * 128, bn = blockIdx.x * 64;
    constexpr int K = 256;
    const int warp_m = wid >> 1, warp_n = wid & 1;

    auto stage = [&](int kc, int s) {
        const int koff = kc * 64;
        const uint32_t base = smb + s * STAGE_;
        for (int i = tid; i < 1024; i += 128) {          // A: 128 rows x 4x16B
            int r = i >> 3, cb = (i & 7) << 4;
            uint32_t dst = (uint32_t)(r * 144 + cb);
            size_t g = (size_t)(bm + r) * K + koff + (cb >> 1);
            cp16_(base + ST_AH + dst, Ahi + g);
            cp16_(base + ST_AL + dst, Alo + g);
        }
        for (int i = tid; i < 512; i += 128) {           // W: 64 rows
            int r = i >> 3, cb = (i & 7) << 4;
            uint32_t dst = (uint32_t)(r * 144 + cb);
            size_t g = (size_t)(bn + r) * K + koff + (cb >> 1);
            cp16_(base + ST_WH + dst, Whi + g);
            cp16_(base + ST_WL + dst, Wlo + g);
        }
        asm volatile("cp.async.commit_group;");
    };

    stage(0, 0);
    stage(1, 1);

    float acc[4][4][4] = {};
    const int lrow = lane & 15;
    const int lcol = (lane >> 4) << 3;

#pragma unroll
    for (int kc = 0; kc < 4; kc++) {
        if (kc == 3) asm volatile("cp.async.wait_group 0;");
        else         asm volatile("cp.async.wait_group 1;");
        __syncthreads();
        const uint32_t sb = smb + (kc & 1) * STAGE_;
#pragma unroll
        for (int ks = 0; ks < 4; ks++) {
            const int k0 = ks * 16;
            uint32_t ah[4][4], al[4][4], bh[2][4], bl[2][4];
#pragma unroll
            for (int i = 0; i < 4; i++) {
                uint32_t off = (uint32_t)((warp_m * 64 + i * 16 + lrow) * SMS_ + k0 + lcol) * 2;
                ldm_x4_(ah[i], sb + ST_AH + off);
                ldm_x4_(al[i], sb + ST_AL + off);
            }
#pragma unroll
            for (int j2 = 0; j2 < 2; j2++) {
                uint32_t off = (uint32_t)((warp_n * 32 + j2 * 16 + lrow) * SMS_ + k0 + lcol) * 2;
                ldm_x4_(bh[j2], sb + ST_WH + off);
                ldm_x4_(bl[j2], sb + ST_WL + off);
            }
#pragma unroll
            for (int i = 0; i < 4; i++) {
#pragma unroll
                for (int j2 = 0; j2 < 2; j2++) {
#pragma unroll
                    for (int s = 0; s < 2; s++) {
                        float* d = acc[i][j2 * 2 + s];
                        mma_(d, ah[i], bh[j2][s], bh[j2][s + 2]);   // hi*hi
                        mma_(d, ah[i], bl[j2][s], bl[j2][s + 2]);   // hi*lo
                        mma_(d, al[i], bh[j2][s], bh[j2][s + 2]);   // lo*hi
                    }
                }
            }
        }
        if (kc < 2) {
            __syncthreads();
            stage(kc + 2, kc & 1);
        }
    }

    const int er = lane >> 2, ec = (lane & 3) << 1;
#pragma unroll
    for (int i = 0; i < 4; i++) {
        int m0 = bm + warp_m * 64 + i * 16 + er;
#pragma unroll
        for (int j = 0; j < 4; j++) {
            int n0 = bn + warp_n * 32 + j * 8 + ec;
            float b0 = bias[n0], b1 = bias[n0 + 1];
            if (EPI == 0) {
#pragma unroll
                for (int h = 0; h < 2; h++) {
                    int m = m0 + h * 8;
                    float2 o;
                    o.x = acc[i][j][2 * h + 0] + b0;
                    o.y = acc[i][j][2 * h + 1] + b1;
                    *(float2*)(Cf + (size_t)m * N + n0) = o;
                }
            } else {
#pragma unroll
                for (int h = 0; h < 2; h++) {
                    int m = m0 + h * 8;
                    float rsv = rs[m];
                    float v0 = elu_(acc[i][j][2 * h + 0] + rsv * b0);
                    float v1 = elu_(acc[i][j][2 * h + 1] + rsv * b1);
                    __nv_bfloat16 h0, l0, h1, l1;
                    split_bf16(v0, &h0, &l0); split_bf16(v1, &h1, &l1);
                    *(__nv_bfloat162*)(Chi + (size_t)m * N + n0) = __nv_bfloat162{h0, h1};
                    *(__nv_bfloat162*)(Clo + (size_t)m * N + n0) = __nv_bfloat162{l0, l1};
                }
            }
        }
    }
}

// ---------------------------------------------------------------------------
// fp32 -> bf16 hi/lo conversion: ALL weights in one launch
// ---------------------------------------------------------------------------
namespace {
constexpr int CV1 = RADIUS_ * FD_ * FD_;
constexpr int CV2 = CV1 + RADIUS_ * GN_ * FD_;
constexpr int CV3 = CV2 + RADIUS_ * GN_ * FD_;
constexpr int CV4 = CV3 + FD_ * FD_;
constexpr int CV5 = CV4 + GN_ * FD_;
constexpr int CV6 = CV5 + GN_ * FD_;
}
__global__ void fp_cvt_all(const float* __restrict__ s1, const float* __restrict__ s2,
                           const float* __restrict__ s3, const float* __restrict__ s4,
                           const float* __restrict__ s5, const float* __restrict__ s6,
                           __nv_bfloat16* __restrict__ h1, __nv_bfloat16* __restrict__ l1,
                           __nv_bfloat16* __restrict__ h2, __nv_bfloat16* __restrict__ l2,
                           __nv_bfloat16* __restrict__ h3, __nv_bfloat16* __restrict__ l3,
                           __nv_bfloat16* __restrict__ h4, __nv_bfloat16* __restrict__ l4,
                           __nv_bfloat16* __restrict__ h5, __nv_bfloat16* __restrict__ l5,
                           __nv_bfloat16* __restrict__ h6, __nv_bfloat16* __restrict__ l6)
{
    int i = blockIdx.x * 256 + threadIdx.x;
    if (i >= CV6) return;
    const float* s; __nv_bfloat16 *h, *l; int o;
    if      (i < CV1) { s = s1; h = h1; l = l1; o = 0;   }
    else if (i < CV2) { s = s2; h = h2; l = l2; o = CV1; }
    else if (i < CV3) { s = s3; h = h3; l = l3; o = CV2; }
    else if (i < CV4) { s = s4; h = h4; l = l4; o = CV3; }
    else if (i < CV5) { s = s5; h = h5; l = l5; o = CV4; }
    else              { s = s6; h = h6; l = l6; o = CV5; }
    int j = i - o;
    split_bf16(s[j], h + j, l + j);
}

// ---------------------------------------------------------------------------
// atom_fc: lrelu(X @ W^T + b); fp32 + bf16 hi/lo + fused self-dot (align_w[0])
// ---------------------------------------------------------------------------
__global__ __launch_bounds__(256)
void fp_atom_fc(const float* __restrict__ X, const float* __restrict__ W,
                const float* __restrict__ bias, const float* __restrict__ vdot,
                float* __restrict__ C,
                __nv_bfloat16* __restrict__ Ch, __nv_bfloat16* __restrict__ Cl,
                float* __restrict__ sd)
{
    __shared__ float sin_[16][IN_ATOM_];
    __shared__ float sred[16][8];
    const int r0 = blockIdx.x * 16;
    for (int i = threadIdx.x; i < 16 * IN_ATOM_; i += 256)
        sin_[i / IN_ATOM_][i % IN_ATOM_] =
            X[(size_t)(r0 + i / IN_ATOM_) * IN_ATOM_ + i % IN_ATOM_];
    __syncthreads();
    const int f = threadIdx.x;
    float acc[16] = {};
    for (int k = 0; k < IN_ATOM_; k++) {
        float wv = __ldg(&W[f * IN_ATOM_ + k]);
#pragma unroll
        for (int r = 0; r < 16; r++) acc[r] += wv * sin_[r][k];
    }
    float bv = bias[f];
    float vw = __ldg(&vdot[f]);
    const int lw = threadIdx.x >> 5, ll = threadIdx.x & 31;
#pragma unroll
    for (int r = 0; r < 16; r++) {
        float v = lrelu_(acc[r] + bv);
        size_t o = (size_t)(r0 + r) * FD_ + f;
        C[o] = v;
        split_bf16(v, Ch + o, Cl + o);
        float p = v * vw;
#pragma unroll
        for (int oo = 16; oo; oo >>= 1) p += __shfl_down_sync(0xffffffffu, p, oo);
        if (ll == 0) sred[r][lw] = p;
    }
    __syncthreads();
    if (threadIdx.x < 16) {
        float s = 0.f;
#pragma unroll
        for (int wdx = 0; wdx < 8; wdx++) s += sred[threadIdx.x][wdx];
        sd[r0 + threadIdx.x] = s;
    }
}

// ---------------------------------------------------------------------------
// FUSED r=0: neighbor_fc + score + softmax + weighted sum.
// Block = 16 atoms, 256 threads (thread = output feature f).
// nbrfeat rows are computed on the fly and NEVER materialized to global.
// ---------------------------------------------------------------------------
__global__ __launch_bounds__(256)
void fp_nbr_attn0(const float* __restrict__ atom_list, const float* __restrict__ bond_list,
                  const int* __restrict__ adeg, const int* __restrict__ bdeg,
                  const float* __restrict__ W, const float* __restrict__ bias,
                  const float* __restrict__ vdot,
                  const float* __restrict__ sd, const float* __restrict__ ab_ptr,
                  __nv_bfloat16* __restrict__ wfh, __nv_bfloat16* __restrict__ wfl,
                  float* __restrict__ wsum)
{
    constexpr int KIN = IN_ATOM_ + IN_BOND_;           // 49
    __shared__ float sin_[16][D_][KIN + 1];            // 16*6*50*4 = 19200 B
    __shared__ float sred[D_][8];
    __shared__ float swd[D_];
    const int a0 = blockIdx.x * 16;
    const int f = threadIdx.x;
    const int lw = f >> 5, ll = f & 31;

    // stage concat(atom_nbr, bond_nbr) inputs for 16 atoms x 6 neighbors
    for (int i = f; i < 16 * D_ * KIN; i += 256) {
        int a = i / (D_ * KIN);
        int rem = i - a * (D_ * KIN);
        int d = rem / KIN, k = rem - d * KIN;
        int m = a0 + a;
        int b = m / L_;
        int rid = m * D_ + d;
        float v;
        if (k < IN_ATOM_) v = atom_list[((size_t)b * L_ + adeg[rid]) * IN_ATOM_ + k];
        else              v = bond_list[((size_t)b * NBONDS_ + bdeg[rid]) * IN_BOND_ + (k - IN_ATOM_)];
        sin_[a][d][k] = v;
    }
    // FC weight row f into registers
    float wreg[KIN];
#pragma unroll
    for (int k = 0; k < KIN; k++) wreg[k] = __ldg(&W[f * KIN + k]);
    const float bv = bias[f];
    const float vw = __ldg(&vdot[f]);
    __syncthreads();

    for (int a = 0; a < 16; a++) {
        const int m = a0 + a;
        float v[D_];
#pragma unroll
        for (int d = 0; d < D_; d++) {
            float acc = bv;
#pragma unroll
            for (int k = 0; k < KIN; k++) acc += wreg[k] * sin_[a][d][k];
            v[d] = lrelu_(acc);
        }
#pragma unroll
        for (int d = 0; d < D_; d++) {
            float p = v[d] * vw;
#pragma unroll
            for (int o = 16; o; o >>= 1) p += __shfl_down_sync(0xffffffffu, p, o);
            if (ll == 0) sred[d][lw] = p;
        }
        __syncthreads();
        if (f == 0) {
            const float ab = ab_ptr[0];
            const float sdv = sd[m];
            float sc[D_], msk[D_];
            float mx = -3.4e38f;
#pragma unroll
            for (int d = 0; d < D_; d++) {
                float ndv = 0.f;
#pragma unroll
                for (int wdx = 0; wdx < 8; wdx++) ndv += sred[d][wdx];
                float s = lrelu_(sdv + ndv + ab);
                bool pad = (adeg[m * D_ + d] == L_ - 1);
                if (pad) s += NEG_;
                msk[d] = pad ? 0.f : 1.f;
                sc[d] = s;
                mx = fmaxf(mx, s);
            }
            float sum = 0.f;
#pragma unroll
            for (int d = 0; d < D_; d++) { float e = expf(sc[d] - mx); sum += e; sc[d] = e; }
            float inv = 1.f / sum, ws = 0.f;
#pragma unroll
            for (int d = 0; d < D_; d++) {
                float wv = sc[d] * inv * msk[d];
                swd[d] = wv;
                ws += wv;
            }
            wsum[m] = ws;
        }
        __syncthreads();
        float accw = 0.f;
#pragma unroll
        for (int d = 0; d < D_; d++) accw += swd[d] * v[d];
        split_bf16(accw, wfh + (size_t)m * FD_ + f, wfl + (size_t)m * FD_ + f);
    }
}

// ---------------------------------------------------------------------------
// FUSED attention for r>=1: score + softmax + weighted sum over act.
// ---------------------------------------------------------------------------
__global__ __launch_bounds__(256)
void fp_attn(const float* __restrict__ sd, const float* __restrict__ nd,
             const int* __restrict__ adeg, const float* __restrict__ ab_ptr,
             const float* __restrict__ src,
             __nv_bfloat16* __restrict__ wfh, __nv_bfloat16* __restrict__ wfl,
             float* __restrict__ wsum)
{
    __shared__ float sw[2][D_];
    __shared__ int sidx[2][D_];
    const int m0 = blockIdx.x * 2;

    if ((threadIdx.x & 127) == 0) {
        const int r = threadIdx.x >> 7;
        const int m = m0 + r;
        const int b = m / L_;
        const float ab = ab_ptr[0];
        const float sdv = sd[m];
        float sc[D_], msk[D_];
        int idxs[D_];
        float mx = -3.4e38f;
#pragma unroll
        for (int d = 0; d < D_; d++) {
            int idx = adeg[m * D_ + d];
            idxs[d] = idx;
            float ndv = nd[b * L_ + idx];
            float s = lrelu_(sdv + ndv + ab);
            bool pad = (idx == L_ - 1);
            if (pad) s += NEG_;
            msk[d] = pad ? 0.f : 1.f;
            sc[d] = s;
            mx = fmaxf(mx, s);
        }
        float sum = 0.f;
#pragma unroll
        for (int d = 0; d < D_; d++) { float e = expf(sc[d] - mx); sum += e; sc[d] = e; }
        float inv = 1.f / sum, ws = 0.f;
#pragma unroll
        for (int d = 0; d < D_; d++) {
            float wv = sc[d] * inv * msk[d];
            sw[r][d] = wv;
            sidx[r][d] = idxs[d];
            ws += wv;
        }
        wsum[m] = ws;
    }
    __syncthreads();

    const int f = threadIdx.x;
#pragma unroll
    for (int r = 0; r < 2; r++) {
        int m = m0 + r;
        int b = m / L_;
        float acc = 0.f;
#pragma unroll
        for (int d = 0; d < D_; d++)
            acc += sw[r][d] * src[(size_t)(b * L_ + sidx[r][d]) * FD_ + f];
        split_bf16(acc, wfh + (size_t)m * FD_ + f, wfl + (size_t)m * FD_ + f);
    }
}

// ---------------------------------------------------------------------------
// GRU gate + fused dot products on act (one block per row, 256 threads).
// ---------------------------------------------------------------------------
__global__ __launch_bounds__(256)
void fp_gru_gate_dot(const float* __restrict__ gi, const float* __restrict__ gh,
                     const float* __restrict__ hin, float* __restrict__ hout,
                     __nv_bfloat16* __restrict__ hh, __nv_bfloat16* __restrict__ hl,
                     float* __restrict__ act,
                     __nv_bfloat16* __restrict__ ah, __nv_bfloat16* __restrict__ al,
                     const float* __restrict__ v0, const float* __restrict__ v1,
                     const float* __restrict__ v2, const float* __restrict__ v3,
                     float* __restrict__ y0, float* __restrict__ y1,
                     float* __restrict__ y2, float* __restrict__ y3)
{
    __shared__ float sred[4][8];
    const int m = blockIdx.x, f = threadIdx.x;
    const size_t g = (size_t)m * FD_ + f;
    const float* gim = gi + (size_t)m * GN_;
    const float* ghm = gh + (size_t)m * GN_;
    float r = sigm_(gim[f] + ghm[f]);
    float z = sigm_(gim[FD_ + f] + ghm[FD_ + f]);
    float n = tanhf(gim[2 * FD_ + f] + r * ghm[2 * FD_ + f]);
    float h = (1.f - z) * n + z * hin[g];
    hout[g] = h;
    if (hh) split_bf16(h, hh + g, hl + g);
    float a = fmaxf(h, 0.f);
    act[g] = a;
    if (ah) split_bf16(a, ah + g, al + g);

    float p0 = a * v0[f];
    float p1 = a * v1[f];
    float p2 = v2 ? a * v2[f] : 0.f;
    float p3 = v3 ? a * v3[f] : 0.f;
#pragma unroll
    for (int o = 16; o; o >>= 1) {
        p0 += __shfl_down_sync(0xffffffffu, p0, o);
        p1 += __shfl_down_sync(0xffffffffu, p1, o);
        p2 += __shfl_down_sync(0xffffffffu, p2, o);
        p3 += __shfl_down_sync(0xffffffffu, p3, o);
    }
    const int lw = f >> 5, ll = f & 31;
    if (ll == 0) { sred[0][lw] = p0; sred[1][lw] = p1; sred[2][lw] = p2; sred[3][lw] = p3; }
    __syncthreads();
    if (f < 4) {
        float s = 0.f;
#pragma unroll
        for (int wdx = 0; wdx < 8; wdx++) s += sred[f][wdx];
        if      (f == 0) y0[m] = s;
        else if (f == 1) y1[m] = s;
        else if (f == 2) { if (y2) y2[m] = s; }
        else             { if (y3) y3[m] = s; }
    }
}

// ---------------------------------------------------------------------------
// Flat GRU gate (final mol step)
// ---------------------------------------------------------------------------
__global__ void fp_gru_gate(const float* __restrict__ gi, const float* __restrict__ gh,
                            const float* __restrict__ hin, float* __restrict__ hout,
                            float* __restrict__ out, int M)
{
    int g = blockIdx.x * blockDim.x + threadIdx.x;
    if (g >= M * FD_) return;
    int m = g / FD_, f = g - m * FD_;
    const float* gim = gi + (size_t)m * GN_;
    const float* ghm = gh + (size_t)m * GN_;
    float r = sigm_(gim[f] + ghm[f]);
    float z = sigm_(gim[FD_ + f] + ghm[FD_ + f]);
    float n = tanhf(gim[2 * FD_ + f] + r * ghm[2 * FD_ + f]);
    float h = (1.f - z) * n + z * hin[g];
    hout[g] = h;
    out[g] = fmaxf(h, 0.f);
}

// ---------------------------------------------------------------------------
// molecule feature init
// ---------------------------------------------------------------------------
__global__ void fp_molfeat(const float* __restrict__ act, const float* __restrict__ amask,
                           float* __restrict__ mf, __nv_bfloat16* __restrict__ mfh,
                           __nv_bfloat16* __restrict__ mfl, float* __restrict__ am)
{
    int b = blockIdx.x, f = threadIdx.x;
    float acc = 0.f;
    for (int l = 0; l < L_; l++)
        acc += act[((size_t)b * L_ + l) * FD_ + f] * amask[b * L_ + l];
    mf[b * FD_ + f] = acc;
    split_bf16(acc, mfh + b * FD_ + f, mfl + b * FD_ + f);
    am[b * FD_ + f] = fmaxf(acc, 0.f);
}

// ---------------------------------------------------------------------------
// Fused (optional GRU gate) + mol score + softmax + context, per-molecule.
// ---------------------------------------------------------------------------
__global__ __launch_bounds__(128)
void fp_molstep(const float* __restrict__ gi, const float* __restrict__ gh,
                float* __restrict__ mf, __nv_bfloat16* __restrict__ mfh,
                __nv_bfloat16* __restrict__ mfl, const float* __restrict__ am_g,
                float* __restrict__ outp,
                const float* __restrict__ maw, const float* __restrict__ mab,
                const float* __restrict__ actdot, const float* __restrict__ amask,
                const float* __restrict__ actT,
                __nv_bfloat16* __restrict__ ctxh, __nv_bfloat16* __restrict__ ctxl, int task)
{
    __shared__ float red[128];
    __shared__ float sam[256];
    __shared__ float sw[128];
    int b = blockIdx.x, t = threadIdx.x;

    if (gi) {
        const float* gim = gi + (size_t)b * GN_;
        const float* ghm = gh + (size_t)b * GN_;
#pragma unroll
        for (int ff = 0; ff < 2; ff++) {
            int f = t + ff * 128;
            size_t g = (size_t)b * FD_ + f;
            float r = sigm_(gim[f] + ghm[f]);
            float z = sigm_(gim[FD_ + f] + ghm[FD_ + f]);
            float n = tanhf(gim[2 * FD_ + f] + r * ghm[2 * FD_ + f]);
            float h = (1.f - z) * n + z * mf[g];
            mf[g] = h;
            split_bf16(h, mfh + g, mfl + g);
            float a = fmaxf(h, 0.f);
            sam[f] = a;
            if (outp) outp[g] = a;
        }
    } else {
        sam[t] = am_g[(size_t)b * FD_ + t];
        sam[t + 128] = am_g[(size_t)b * FD_ + t + 128];
    }
    __syncthreads();

    const float* ms = maw + task * 2 * FD_;
    float p = sam[t] * ms[t] + sam[t + 128] * ms[128 + t];
    red[t] = p; __syncthreads();
    for (int st = 64; st; st >>= 1) { if (t < st) red[t] += red[t + st]; __syncthreads(); }
    float sdv = red[0]; __syncthreads();
    float amv = amask[b * L_ + t];
    float s = lrelu_(sdv + actdot[task * BL_ + b * L_ + t] + mab[task]);
    if (amv == 0.f) s += NEG_;
    red[t] = s; __syncthreads();
    for (int st = 64; st; st >>= 1) { if (t < st) red[t] = fmaxf(red[t], red[t + st]); __syncthreads(); }
    float mx = red[0]; __syncthreads();
    float e = expf(s - mx);
    red[t] = e; __syncthreads();
    for (int st = 64; st; st >>= 1) { if (t < st) red[t] += red[t + st]; __syncthreads(); }
    float sum = red[0];
    sw[t] = e / sum * amv;
    __syncthreads();
    float a0 = 0.f, a1 = 0.f;
    for (int l = 0; l < L_; l++) {
        float wv = sw[l];
        const float* row = actT + ((size_t)b * L_ + l) * FD_;
        a0 += wv * row[t];
        a1 += wv * row[t + 128];
    }
    a0 = elu_(a0); a1 = elu_(a1);
    split_bf16(a0, ctxh + b * FD_ + t, ctxl + b * FD_ + t);
    split_bf16(a1, ctxh + b * FD_ + 128 + t, ctxl + b * FD_ + 128 + t);
}

// ---------------------------------------------------------------------------
// Host launch sequence
// ---------------------------------------------------------------------------
extern "C" void kernel_launch(void* const* d_in, const int* in_sizes, int n_in,
                              void* d_out, int out_size)
{
    const float* atom_list = (const float*)d_in[0];
    const float* bond_list = (const float*)d_in[1];
    const int*   adeg      = (const int*)d_in[2];
    const int*   bdeg      = (const int*)d_in[3];
    const float* amask     = (const float*)d_in[4];
    const float* atom_fc_w = (const float*)d_in[5];
    const float* atom_fc_b = (const float*)d_in[6];
    const float* nbr_fc_w  = (const float*)d_in[7];
    const float* nbr_fc_b  = (const float*)d_in[8];
    const float* align_w   = (const float*)d_in[9];
    const float* align_b   = (const float*)d_in[10];
    const float* attend_w  = (const float*)d_in[11];
    const float* attend_b  = (const float*)d_in[12];
    const float* gru_wih   = (const float*)d_in[13];
    const float* gru_whh   = (const float*)d_in[14];
    const float* gru_bih   = (const float*)d_in[15];
    const float* gru_bhh   = (const float*)d_in[16];
    const float* mgru_wih  = (const float*)d_in[17];
    const float* mgru_whh  = (const float*)d_in[18];
    const float* mgru_bih  = (const float*)d_in[19];
    const float* mgru_bhh  = (const float*)d_in[20];
    const float* mal_w     = (const float*)d_in[21];
    const float* mal_b     = (const float*)d_in[22];
    const float* mat_w     = (const float*)d_in[23];
    const float* mat_b     = (const float*)d_in[24];
    float* out = (float*)d_out;

    cudaFuncSetAttribute((const void*)tgemm<0>, cudaFuncAttributeMaxDynamicSharedMemorySize, SM_TOTAL);
    cudaFuncSetAttribute((const void*)tgemm<2>, cudaFuncAttributeMaxDynamicSharedMemorySize, SM_TOTAL);

#define SYM(p, s) cudaGetSymbolAddress((void**)&p, s)
    float *p_af, *p_h, *p_act, *p_actT, *p_gi, *p_gh, *p_sd, *p_nd,
          *p_ws, *p_ad, *p_mf, *p_am, *p_mgi, *p_mgh;
    __nv_bfloat16 *p_afh, *p_afl, *p_wfh, *p_wfl, *p_cxh, *p_cxl, *p_hh, *p_hl,
                  *p_ach, *p_acl, *p_mch, *p_mcl, *p_mfh, *p_mfl,
                  *w_atth, *w_attl, *w_ihh, *w_ihl, *w_hhh, *w_hhl,
                  *w_math, *w_matl, *w_mihh, *w_mihl, *w_mhhh, *w_mhhl;
    SYM(p_af, g_atomfeat); SYM(p_h, g_h); SYM(p_act, g_act);
    SYM(p_actT, g_actT); SYM(p_gi, g_gi); SYM(p_gh, g_gh);
    SYM(p_sd, g_sd); SYM(p_nd, g_nd); SYM(p_ws, g_wsum);
    SYM(p_ad, g_actdot); SYM(p_mf, g_molfeat); SYM(p_am, g_actmol);
    SYM(p_mgi, g_mgi); SYM(p_mgh, g_mgh);
    SYM(p_afh, g_af_h); SYM(p_afl, g_af_l); SYM(p_wfh, g_wf_h); SYM(p_wfl, g_wf_l);
    SYM(p_cxh, g_ctx_h); SYM(p_cxl, g_ctx_l); SYM(p_hh, g_h_h); SYM(p_hl, g_h_l);
    SYM(p_ach, g_act_h); SYM(p_acl, g_act_l); SYM(p_mch, g_mctx_h); SYM(p_mcl, g_mctx_l);
    SYM(p_mfh, g_mf_h); SYM(p_mfl, g_mf_l);
    SYM(w_atth, g_watt_h); SYM(w_attl, g_watt_l); SYM(w_ihh, g_wih_h); SYM(w_ihl, g_wih_l);
    SYM(w_hhh, g_whh_h); SYM(w_hhl, g_whh_l); SYM(w_math, g_mat_h); SYM(w_matl, g_mat_l);
    SYM(w_mihh, g_mih_h); SYM(w_mihl, g_mih_l); SYM(w_mhhh, g_mhh_h); SYM(w_mhhl, g_mhh_l);
#undef SYM

    fp_cvt_all<<<(CV6 + 255) / 256, 256>>>(attend_w, gru_wih, gru_whh, mat_w, mgru_wih, mgru_whh,
                                           w_atth, w_attl, w_ihh, w_ihl, w_hhh, w_hhl,
                                           w_math, w_matl, w_mihh, w_mihl, w_mhhh, w_mhhl);

    fp_atom_fc<<<BL_ / 16, 256>>>(atom_list, atom_fc_w, atom_fc_b, align_w,
                                  p_af, p_afh, p_afl, p_sd);
    // fused neighbor_fc + r=0 attention (no nbrfeat materialization)
    fp_nbr_attn0<<<BL_ / 16, 256>>>(atom_list, bond_list, adeg, bdeg,
                                    nbr_fc_w, nbr_fc_b, align_w + 256,
                                    p_sd, align_b, p_wfh, p_wfl, p_ws);

    const dim3 gctx(FD_ / 64, BL_ / 128, 1);      // 16384 x 256
    const dim3 ggru(GN_ / 64, BL_ / 128, 2);      // 16384 x 768, batched gi/gh
    const dim3 gmol(GN_ / 64, 1, 2);              // 128 x 768, batched gi/gh

    // --- radius loop ---
    for (int r = 0; r < RADIUS_; r++) {
        const __nv_bfloat16* hprev_h = (r == 0) ? p_afh : p_hh;
        const __nv_bfloat16* hprev_l = (r == 0) ? p_afl : p_hl;
        const float* hprev_f = (r == 0) ? p_af : p_h;

        if (r > 0) {
            fp_attn<<<BL_ / 2, 256>>>(p_sd, p_nd, adeg, align_b + r, p_act,
                                      p_wfh, p_wfl, p_ws);
        }
        tgemm<2><<<gctx, 128, SM_TOTAL>>>(p_wfh, p_wfl, nullptr, nullptr,
                                          w_atth + (size_t)r * FD_ * FD_, w_attl + (size_t)r * FD_ * FD_,
                                          nullptr, nullptr,
                                          attend_b + r * FD_, nullptr, p_ws,
                                          nullptr, nullptr, p_cxh, p_cxl, FD_);
        tgemm<0><<<ggru, 128, SM_TOTAL>>>(p_cxh, p_cxl, hprev_h, hprev_l,
                                          w_ihh + (size_t)r * GN_ * FD_, w_ihl + (size_t)r * GN_ * FD_,
                                          w_hhh + (size_t)r * GN_ * FD_, w_hhl + (size_t)r * GN_ * FD_,
                                          gru_bih + r * GN_, gru_bhh + r * GN_, nullptr,
                                          p_gi, p_gh, nullptr, nullptr, GN_);
        bool last = (r == RADIUS_ - 1);
        if (!last) {
            fp_gru_gate_dot<<<BL_, 256>>>(p_gi, p_gh, hprev_f, p_h, p_hh, p_hl,
                                          p_act, nullptr, nullptr,
                                          align_w + (r + 1) * 512, align_w + (r + 1) * 512 + 256,
                                          nullptr, nullptr,
                                          p_sd, p_nd, nullptr, nullptr);
        } else {
            fp_gru_gate_dot<<<BL_, 256>>>(p_gi, p_gh, hprev_f, p_h, p_hh, p_hl,
                                          p_act, p_ach, p_acl,
                                          mal_w + 256, mal_w + 512 + 256,
                                          mal_w + 1024 + 256, mal_w + 1536 + 256,
                                          p_ad, p_ad + BL_, p_ad + 2 * BL_, p_ad + 3 * BL_);
        }
    }

    // --- molecule phase ---
    fp_molfeat<<<B_, FD_>>>(p_act, amask, p_mf, p_mfh, p_mfl, p_am);
    tgemm<0><<<gctx, 128, SM_TOTAL>>>(p_ach, p_acl, nullptr, nullptr,
                                      w_math, w_matl, nullptr, nullptr,
                                      mat_b, nullptr, nullptr,
                                      p_actT, nullptr, nullptr, nullptr, FD_);

    for (int it = 0; it < TASKS_ * T_; it++) {
        int task = it >> 1;
        const float* gi_arg = (it == 0) ? nullptr : p_mgi;
        float* outp = (it > 0 && ((it - 1) & 1)) ? out + (size_t)((it - 1) >> 1) * B_ * FD_
                                                 : nullptr;
        fp_molstep<<<B_, 128>>>(gi_arg, p_mgh, p_mf, p_mfh, p_mfl, p_am, outp,
                                mal_w, mal_b, p_ad, amask, p_actT, p_mch, p_mcl, task);
        tgemm<0><<<gmol, 128, SM_TOTAL>>>(p_mch, p_mcl, p_mfh, p_mfl,
                                          w_mihh, w_mihl, w_mhhh, w_mhhl,
                                          mgru_bih, mgru_bhh, nullptr,
                                          p_mgi, p_mgh, nullptr, nullptr, GN_);
    }
    fp_gru_gate<<<B_ * FD_ / 256, 256>>>(p_mgi, p_mgh, p_mf, p_mf,
                                         out + (size_t)(TASKS_ - 1) * B_ * FD_, B_);
}

// round 12
// speedup vs baseline: 1.0698x; 1.0209x over previous
#include <cuda_runtime.h>
#include <cuda_bf16.h>
#include <math.h>
#include <stdint.h>

// ---------------------------------------------------------------------------
// Problem constants
// ---------------------------------------------------------------------------
namespace {
constexpr int B_ = 128, L_ = 128, D_ = 6, FD_ = 256;
constexpr int IN_ATOM_ = 39, IN_BOND_ = 10, NBONDS_ = 256;
constexpr int RADIUS_ = 3, TASKS_ = 4, T_ = 2;
constexpr int BL_ = B_ * L_;        // 16384
constexpr float NEG_ = -9e8f;
constexpr int GN_ = 3 * FD_;        // 768
}

// ---------------------------------------------------------------------------
// Scratch buffers (device globals; no allocations allowed)
// ---------------------------------------------------------------------------
__device__ float g_atomfeat[BL_ * FD_];
__device__ float g_h       [BL_ * FD_];
__device__ float g_act     [BL_ * FD_];
__device__ float g_actT    [BL_ * FD_];
__device__ float g_gi      [BL_ * GN_];
__device__ float g_gh      [BL_ * GN_];
__device__ float g_sd      [BL_];
__device__ float g_nd      [BL_];
__device__ float g_wsum    [BL_];
__device__ float g_actdot  [TASKS_ * BL_];
__device__ float g_molfeat [B_ * FD_];
__device__ float g_actmol  [B_ * FD_];
__device__ float g_mgi     [B_ * GN_];
__device__ float g_mgh     [B_ * GN_];

// bf16 hi/lo activation buffers (16B aligned for uint4 / cp.async staging)
__device__ __align__(16) __nv_bfloat16 g_af_h [BL_ * FD_];
__device__ __align__(16) __nv_bfloat16 g_af_l [BL_ * FD_];
__device__ __align__(16) __nv_bfloat16 g_wf_h [BL_ * FD_];
__device__ __align__(16) __nv_bfloat16 g_wf_l [BL_ * FD_];
__device__ __align__(16) __nv_bfloat16 g_ctx_h[BL_ * FD_];
__device__ __align__(16) __nv_bfloat16 g_ctx_l[BL_ * FD_];
__device__ __align__(16) __nv_bfloat16 g_h_h  [BL_ * FD_];
__device__ __align__(16) __nv_bfloat16 g_h_l  [BL_ * FD_];
__device__ __align__(16) __nv_bfloat16 g_act_h[BL_ * FD_];
__device__ __align__(16) __nv_bfloat16 g_act_l[BL_ * FD_];
__device__ __align__(16) __nv_bfloat16 g_mctx_h[B_ * FD_];
__device__ __align__(16) __nv_bfloat16 g_mctx_l[B_ * FD_];
__device__ __align__(16) __nv_bfloat16 g_mf_h [B_ * FD_];
__device__ __align__(16) __nv_bfloat16 g_mf_l [B_ * FD_];
// bf16 hi/lo weights
__device__ __align__(16) __nv_bfloat16 g_watt_h[RADIUS_ * FD_ * FD_];
__device__ __align__(16) __nv_bfloat16 g_watt_l[RADIUS_ * FD_ * FD_];
__device__ __align__(16) __nv_bfloat16 g_wih_h [RADIUS_ * GN_ * FD_];
__device__ __align__(16) __nv_bfloat16 g_wih_l [RADIUS_ * GN_ * FD_];
__device__ __align__(16) __nv_bfloat16 g_whh_h [RADIUS_ * GN_ * FD_];
__device__ __align__(16) __nv_bfloat16 g_whh_l [RADIUS_ * GN_ * FD_];
__device__ __align__(16) __nv_bfloat16 g_mat_h [FD_ * FD_];
__device__ __align__(16) __nv_bfloat16 g_mat_l [FD_ * FD_];
__device__ __align__(16) __nv_bfloat16 g_mih_h [GN_ * FD_];
__device__ __align__(16) __nv_bfloat16 g_mih_l [GN_ * FD_];
__device__ __align__(16) __nv_bfloat16 g_mhh_h [GN_ * FD_];
__device__ __align__(16) __nv_bfloat16 g_mhh_l [GN_ * FD_];

__device__ __forceinline__ float lrelu_(float x) { return x > 0.f ? x : 0.01f * x; }
__device__ __forceinline__ float elu_(float x)   { return x > 0.f ? x : expm1f(x); }
__device__ __forceinline__ float sigm_(float x)  { return 1.f / (1.f + expf(-x)); }

__device__ __forceinline__ void split_bf16(float v, __nv_bfloat16* hp, __nv_bfloat16* lp) {
    __nv_bfloat16 h = __float2bfloat16(v);
    *hp = h;
    *lp = __float2bfloat16(v - __bfloat162float(h));
}

// ---------------------------------------------------------------------------
// mma.sync + ldmatrix + cp.async helpers (baseline PTX, compute_103-safe)
// ---------------------------------------------------------------------------
__device__ __forceinline__ uint32_t smem_u32_(const void* p) {
    uint32_t a;
    asm("{ .reg .u64 t; cvta.to.shared.u64 t, %1; cvt.u32.u64 %0, t; }" : "=r"(a) : "l"(p));
    return a;
}
__device__ __forceinline__ void ldm_x4_(uint32_t* r, uint32_t addr) {
    asm volatile("ldmatrix.sync.aligned.m8n8.x4.shared.b16 {%0,%1,%2,%3}, [%4];"
                 : "=r"(r[0]), "=r"(r[1]), "=r"(r[2]), "=r"(r[3]) : "r"(addr));
}
__device__ __forceinline__ void mma_(float* d, const uint32_t* a, uint32_t b0, uint32_t b1) {
    asm volatile(
        "mma.sync.aligned.m16n8k16.row.col.f32.bf16.bf16.f32 "
        "{%0,%1,%2,%3}, {%4,%5,%6,%7}, {%8,%9}, {%0,%1,%2,%3};"
        : "+f"(d[0]), "+f"(d[1]), "+f"(d[2]), "+f"(d[3])
        : "r"(a[0]), "r"(a[1]), "r"(a[2]), "r"(a[3]), "r"(b0), "r"(b1));
}
__device__ __forceinline__ void cp16_(uint32_t dst, const void* src) {
    asm volatile("cp.async.cg.shared.global [%0], [%1], 16;" :: "r"(dst), "l"(src));
}

// ---------------------------------------------------------------------------
// Pipelined HMMA GEMM: C = (Ahi+Alo) @ (Whi+Wlo)^T (bf16x3 emulation)
// CTA: 256 thr / 8 warps (4x2 grid), tile 128x64, warp tile 32x32.
// Same smem layout/pipeline as R9 (110,592 B, 2 CTA/SM) but 16 warps/SM.
// EPI 0: Cf = acc + bias[n]  (fp32)
// EPI 2: elu(acc + rs[m]*bias[n]) -> Chi/Clo bf16 split
// gridDim.z==2 selects second (A2/W2/bias2/C2f) problem.
// ---------------------------------------------------------------------------
namespace {
constexpr int SMS_ = 72;                       // bf16 row stride (144 B)
constexpr int ST_AH = 0;
constexpr int ST_AL = 128 * SMS_ * 2;          // 18432
constexpr int ST_WH = 2 * 128 * SMS_ * 2;      // 36864
constexpr int ST_WL = ST_WH + 64 * SMS_ * 2;   // 46080
constexpr int STAGE_ = ST_WL + 64 * SMS_ * 2;  // 55296
constexpr int SM_TOTAL = 2 * STAGE_;           // 110592
}

template <int EPI>
__global__ __launch_bounds__(256)
void tgemm(const __nv_bfloat16* __restrict__ Ahi, const __nv_bfloat16* __restrict__ Alo,
           const __nv_bfloat16* __restrict__ A2hi, const __nv_bfloat16* __restrict__ A2lo,
           const __nv_bfloat16* __restrict__ Whi, const __nv_bfloat16* __restrict__ Wlo,
           const __nv_bfloat16* __restrict__ W2hi, const __nv_bfloat16* __restrict__ W2lo,
           const float* __restrict__ bias, const float* __restrict__ bias2,
           const float* __restrict__ rs,
           float* __restrict__ Cf, float* __restrict__ C2f,
           __nv_bfloat16* __restrict__ Chi, __nv_bfloat16* __restrict__ Clo,
           int N)
{
    extern __shared__ char sm[];
    const uint32_t smb = smem_u32_(sm);
    const int tid = threadIdx.x, wid = tid >> 5, lane = tid & 31;
    if (blockIdx.z) { Ahi = A2hi; Alo = A2lo; Whi = W2hi; Wlo = W2lo; bias = bias2; Cf = C2f; }
    const int bm = blockIdx.y * 128, bn = blockIdx.x * 64;
    constexpr int K = 256;
    const int warp_m = wid >> 1, warp_n = wid & 1;   // 4x2 warp grid, warp tile 32x32

    auto stage = [&](int kc, int s) {
        const int koff = kc * 64;
        const uint32_t base = smb + s * STAGE_;
        for (int i = tid; i < 1024; i += 256) {          // A: 128 rows x 4x16B
            int r = i >> 3, cb = (i & 7) << 4;
            uint32_t dst = (uint32_t)(r * 144 + cb);
            size_t g = (size_t)(bm + r) * K + koff + (cb >> 1);
            cp16_(base + ST_AH + dst, Ahi + g);
            cp16_(base + ST_AL + dst, Alo + g);
        }
        for (int i = tid; i < 512; i += 256) {           // W: 64 rows
            int r = i >> 3, cb = (i & 7) << 4;
            uint32_t dst = (uint32_t)(r * 144 + cb);
            size_t g = (size_t)(bn + r) * K + koff + (cb >> 1);
            cp16_(base + ST_WH + dst, Whi + g);
            cp16_(base + ST_WL + dst, Wlo + g);
        }
        asm volatile("cp.async.commit_group;");
    };

    stage(0, 0);
    stage(1, 1);

    float acc[2][4][4] = {};
    const int lrow = lane & 15;
    const int lcol = (lane >> 4) << 3;

#pragma unroll
    for (int kc = 0; kc < 4; kc++) {
        if (kc == 3) asm volatile("cp.async.wait_group 0;");
        else         asm volatile("cp.async.wait_group 1;");
        __syncthreads();
        const uint32_t sb = smb + (kc & 1) * STAGE_;
#pragma unroll
        for (int ks = 0; ks < 4; ks++) {
            const int k0 = ks * 16;
            uint32_t ah[2][4], al[2][4], bh[2][4], bl[2][4];
#pragma unroll
            for (int i = 0; i < 2; i++) {
                uint32_t off = (uint32_t)((warp_m * 32 + i * 16 + lrow) * SMS_ + k0 + lcol) * 2;
                ldm_x4_(ah[i], sb + ST_AH + off);
                ldm_x4_(al[i], sb + ST_AL + off);
            }
#pragma unroll
            for (int j2 = 0; j2 < 2; j2++) {
                uint32_t off = (uint32_t)((warp_n * 32 + j2 * 16 + lrow) * SMS_ + k0 + lcol) * 2;
                ldm_x4_(bh[j2], sb + ST_WH + off);
                ldm_x4_(bl[j2], sb + ST_WL + off);
            }
#pragma unroll
            for (int i = 0; i < 2; i++) {
#pragma unroll
                for (int j2 = 0; j2 < 2; j2++) {
#pragma unroll
                    for (int s = 0; s < 2; s++) {
                        float* d = acc[i][j2 * 2 + s];
                        mma_(d, ah[i], bh[j2][s], bh[j2][s + 2]);   // hi*hi
                        mma_(d, ah[i], bl[j2][s], bl[j2][s + 2]);   // hi*lo
                        mma_(d, al[i], bh[j2][s], bh[j2][s + 2]);   // lo*hi
                    }
                }
            }
        }
        if (kc < 2) {
            __syncthreads();
            stage(kc + 2, kc & 1);
        }
    }

    const int er = lane >> 2, ec = (lane & 3) << 1;
#pragma unroll
    for (int i = 0; i < 2; i++) {
        int m0 = bm + warp_m * 32 + i * 16 + er;
#pragma unroll
        for (int j = 0; j < 4; j++) {
            int n0 = bn + warp_n * 32 + j * 8 + ec;
            float b0 = bias[n0], b1 = bias[n0 + 1];
            if (EPI == 0) {
#pragma unroll
                for (int h = 0; h < 2; h++) {
                    int m = m0 + h * 8;
                    float2 o;
                    o.x = acc[i][j][2 * h + 0] + b0;
                    o.y = acc[i][j][2 * h + 1] + b1;
                    *(float2*)(Cf + (size_t)m * N + n0) = o;
                }
            } else {
#pragma unroll
                for (int h = 0; h < 2; h++) {
                    int m = m0 + h * 8;
                    float rsv = rs[m];
                    float v0 = elu_(acc[i][j][2 * h + 0] + rsv * b0);
                    float v1 = elu_(acc[i][j][2 * h + 1] + rsv * b1);
                    __nv_bfloat16 h0, l0, h1, l1;
                    split_bf16(v0, &h0, &l0); split_bf16(v1, &h1, &l1);
                    *(__nv_bfloat162*)(Chi + (size_t)m * N + n0) = __nv_bfloat162{h0, h1};
                    *(__nv_bfloat162*)(Clo + (size_t)m * N + n0) = __nv_bfloat162{l0, l1};
                }
            }
        }
    }
}

// ---------------------------------------------------------------------------
// fp32 -> bf16 hi/lo conversion: ALL weights in one launch
// ---------------------------------------------------------------------------
namespace {
constexpr int CV1 = RADIUS_ * FD_ * FD_;
constexpr int CV2 = CV1 + RADIUS_ * GN_ * FD_;
constexpr int CV3 = CV2 + RADIUS_ * GN_ * FD_;
constexpr int CV4 = CV3 + FD_ * FD_;
constexpr int CV5 = CV4 + GN_ * FD_;
constexpr int CV6 = CV5 + GN_ * FD_;
}
__global__ void fp_cvt_all(const float* __restrict__ s1, const float* __restrict__ s2,
                           const float* __restrict__ s3, const float* __restrict__ s4,
                           const float* __restrict__ s5, const float* __restrict__ s6,
                           __nv_bfloat16* __restrict__ h1, __nv_bfloat16* __restrict__ l1,
                           __nv_bfloat16* __restrict__ h2, __nv_bfloat16* __restrict__ l2,
                           __nv_bfloat16* __restrict__ h3, __nv_bfloat16* __restrict__ l3,
                           __nv_bfloat16* __restrict__ h4, __nv_bfloat16* __restrict__ l4,
                           __nv_bfloat16* __restrict__ h5, __nv_bfloat16* __restrict__ l5,
                           __nv_bfloat16* __restrict__ h6, __nv_bfloat16* __restrict__ l6)
{
    int i = blockIdx.x * 256 + threadIdx.x;
    if (i >= CV6) return;
    const float* s; __nv_bfloat16 *h, *l; int o;
    if      (i < CV1) { s = s1; h = h1; l = l1; o = 0;   }
    else if (i < CV2) { s = s2; h = h2; l = l2; o = CV1; }
    else if (i < CV3) { s = s3; h = h3; l = l3; o = CV2; }
    else if (i < CV4) { s = s4; h = h4; l = l4; o = CV3; }
    else if (i < CV5) { s = s5; h = h5; l = l5; o = CV4; }
    else              { s = s6; h = h6; l = l6; o = CV5; }
    int j = i - o;
    split_bf16(s[j], h + j, l + j);
}

// ---------------------------------------------------------------------------
// atom_fc: lrelu(X @ W^T + b); fp32 + bf16 hi/lo + fused self-dot (align_w[0])
// ---------------------------------------------------------------------------
__global__ __launch_bounds__(256)
void fp_atom_fc(const float* __restrict__ X, const float* __restrict__ W,
                const float* __restrict__ bias, const float* __restrict__ vdot,
                float* __restrict__ C,
                __nv_bfloat16* __restrict__ Ch, __nv_bfloat16* __restrict__ Cl,
                float* __restrict__ sd)
{
    __shared__ float sin_[16][IN_ATOM_];
    __shared__ float sred[16][8];
    const int r0 = blockIdx.x * 16;
    for (int i = threadIdx.x; i < 16 * IN_ATOM_; i += 256)
        sin_[i / IN_ATOM_][i % IN_ATOM_] =
            X[(size_t)(r0 + i / IN_ATOM_) * IN_ATOM_ + i % IN_ATOM_];
    __syncthreads();
    const int f = threadIdx.x;
    float acc[16] = {};
    for (int k = 0; k < IN_ATOM_; k++) {
        float wv = __ldg(&W[f * IN_ATOM_ + k]);
#pragma unroll
        for (int r = 0; r < 16; r++) acc[r] += wv * sin_[r][k];
    }
    float bv = bias[f];
    float vw = __ldg(&vdot[f]);
    const int lw = threadIdx.x >> 5, ll = threadIdx.x & 31;
#pragma unroll
    for (int r = 0; r < 16; r++) {
        float v = lrelu_(acc[r] + bv);
        size_t o = (size_t)(r0 + r) * FD_ + f;
        C[o] = v;
        split_bf16(v, Ch + o, Cl + o);
        float p = v * vw;
#pragma unroll
        for (int oo = 16; oo; oo >>= 1) p += __shfl_down_sync(0xffffffffu, p, oo);
        if (ll == 0) sred[r][lw] = p;
    }
    __syncthreads();
    if (threadIdx.x < 16) {
        float s = 0.f;
#pragma unroll
        for (int wdx = 0; wdx < 8; wdx++) s += sred[threadIdx.x][wdx];
        sd[r0 + threadIdx.x] = s;
    }
}

// ---------------------------------------------------------------------------
// FUSED r=0: neighbor_fc + score + softmax + weighted sum.
// ---------------------------------------------------------------------------
__global__ __launch_bounds__(256)
void fp_nbr_attn0(const float* __restrict__ atom_list, const float* __restrict__ bond_list,
                  const int* __restrict__ adeg, const int* __restrict__ bdeg,
                  const float* __restrict__ W, const float* __restrict__ bias,
                  const float* __restrict__ vdot,
                  const float* __restrict__ sd, const float* __restrict__ ab_ptr,
                  __nv_bfloat16* __restrict__ wfh, __nv_bfloat16* __restrict__ wfl,
                  float* __restrict__ wsum)
{
    constexpr int KIN = IN_ATOM_ + IN_BOND_;           // 49
    __shared__ float sin_[16][D_][KIN + 1];
    __shared__ float sred[D_][8];
    __shared__ float swd[D_];
    const int a0 = blockIdx.x * 16;
    const int f = threadIdx.x;
    const int lw = f >> 5, ll = f & 31;

    for (int i = f; i < 16 * D_ * KIN; i += 256) {
        int a = i / (D_ * KIN);
        int rem = i - a * (D_ * KIN);
        int d = rem / KIN, k = rem - d * KIN;
        int m = a0 + a;
        int b = m / L_;
        int rid = m * D_ + d;
        float v;
        if (k < IN_ATOM_) v = atom_list[((size_t)b * L_ + adeg[rid]) * IN_ATOM_ + k];
        else              v = bond_list[((size_t)b * NBONDS_ + bdeg[rid]) * IN_BOND_ + (k - IN_ATOM_)];
        sin_[a][d][k] = v;
    }
    float wreg[KIN];
#pragma unroll
    for (int k = 0; k < KIN; k++) wreg[k] = __ldg(&W[f * KIN + k]);
    const float bv = bias[f];
    const float vw = __ldg(&vdot[f]);
    __syncthreads();

    for (int a = 0; a < 16; a++) {
        const int m = a0 + a;
        float v[D_];
#pragma unroll
        for (int d = 0; d < D_; d++) {
            float acc = bv;
#pragma unroll
            for (int k = 0; k < KIN; k++) acc += wreg[k] * sin_[a][d][k];
            v[d] = lrelu_(acc);
        }
#pragma unroll
        for (int d = 0; d < D_; d++) {
            float p = v[d] * vw;
#pragma unroll
            for (int o = 16; o; o >>= 1) p += __shfl_down_sync(0xffffffffu, p, o);
            if (ll == 0) sred[d][lw] = p;
        }
        __syncthreads();
        if (f == 0) {
            const float ab = ab_ptr[0];
            const float sdv = sd[m];
            float sc[D_], msk[D_];
            float mx = -3.4e38f;
#pragma unroll
            for (int d = 0; d < D_; d++) {
                float ndv = 0.f;
#pragma unroll
                for (int wdx = 0; wdx < 8; wdx++) ndv += sred[d][wdx];
                float s = lrelu_(sdv + ndv + ab);
                bool pad = (adeg[m * D_ + d] == L_ - 1);
                if (pad) s += NEG_;
                msk[d] = pad ? 0.f : 1.f;
                sc[d] = s;
                mx = fmaxf(mx, s);
            }
            float sum = 0.f;
#pragma unroll
            for (int d = 0; d < D_; d++) { float e = expf(sc[d] - mx); sum += e; sc[d] = e; }
            float inv = 1.f / sum, ws = 0.f;
#pragma unroll
            for (int d = 0; d < D_; d++) {
                float wv = sc[d] * inv * msk[d];
                swd[d] = wv;
                ws += wv;
            }
            wsum[m] = ws;
        }
        __syncthreads();
        float accw = 0.f;
#pragma unroll
        for (int d = 0; d < D_; d++) accw += swd[d] * v[d];
        split_bf16(accw, wfh + (size_t)m * FD_ + f, wfl + (size_t)m * FD_ + f);
    }
}

// ---------------------------------------------------------------------------
// FUSED attention for r>=1: score + softmax + weighted sum over act.
// ---------------------------------------------------------------------------
__global__ __launch_bounds__(256)
void fp_attn(const float* __restrict__ sd, const float* __restrict__ nd,
             const int* __restrict__ adeg, const float* __restrict__ ab_ptr,
             const float* __restrict__ src,
             __nv_bfloat16* __restrict__ wfh, __nv_bfloat16* __restrict__ wfl,
             float* __restrict__ wsum)
{
    __shared__ float sw[2][D_];
    __shared__ int sidx[2][D_];
    const int m0 = blockIdx.x * 2;

    if ((threadIdx.x & 127) == 0) {
        const int r = threadIdx.x >> 7;
        const int m = m0 + r;
        const int b = m / L_;
        const float ab = ab_ptr[0];
        const float sdv = sd[m];
        float sc[D_], msk[D_];
        int idxs[D_];
        float mx = -3.4e38f;
#pragma unroll
        for (int d = 0; d < D_; d++) {
            int idx = adeg[m * D_ + d];
            idxs[d] = idx;
            float ndv = nd[b * L_ + idx];
            float s = lrelu_(sdv + ndv + ab);
            bool pad = (idx == L_ - 1);
            if (pad) s += NEG_;
            msk[d] = pad ? 0.f : 1.f;
            sc[d] = s;
            mx = fmaxf(mx, s);
        }
        float sum = 0.f;
#pragma unroll
        for (int d = 0; d < D_; d++) { float e = expf(sc[d] - mx); sum += e; sc[d] = e; }
        float inv = 1.f / sum, ws = 0.f;
#pragma unroll
        for (int d = 0; d < D_; d++) {
            float wv = sc[d] * inv * msk[d];
            sw[r][d] = wv;
            sidx[r][d] = idxs[d];
            ws += wv;
        }
        wsum[m] = ws;
    }
    __syncthreads();

    const int f = threadIdx.x;
#pragma unroll
    for (int r = 0; r < 2; r++) {
        int m = m0 + r;
        int b = m / L_;
        float acc = 0.f;
#pragma unroll
        for (int d = 0; d < D_; d++)
            acc += sw[r][d] * src[(size_t)(b * L_ + sidx[r][d]) * FD_ + f];
        split_bf16(acc, wfh + (size_t)m * FD_ + f, wfl + (size_t)m * FD_ + f);
    }
}

// ---------------------------------------------------------------------------
// GRU gate + fused dot products on act (one block per row, 256 threads).
// ---------------------------------------------------------------------------
__global__ __launch_bounds__(256)
void fp_gru_gate_dot(const float* __restrict__ gi, const float* __restrict__ gh,
                     const float* __restrict__ hin, float* __restrict__ hout,
                     __nv_bfloat16* __restrict__ hh, __nv_bfloat16* __restrict__ hl,
                     float* __restrict__ act,
                     __nv_bfloat16* __restrict__ ah, __nv_bfloat16* __restrict__ al,
                     const float* __restrict__ v0, const float* __restrict__ v1,
                     const float* __restrict__ v2, const float* __restrict__ v3,
                     float* __restrict__ y0, float* __restrict__ y1,
                     float* __restrict__ y2, float* __restrict__ y3)
{
    __shared__ float sred[4][8];
    const int m = blockIdx.x, f = threadIdx.x;
    const size_t g = (size_t)m * FD_ + f;
    const float* gim = gi + (size_t)m * GN_;
    const float* ghm = gh + (size_t)m * GN_;
    float r = sigm_(gim[f] + ghm[f]);
    float z = sigm_(gim[FD_ + f] + ghm[FD_ + f]);
    float n = tanhf(gim[2 * FD_ + f] + r * ghm[2 * FD_ + f]);
    float h = (1.f - z) * n + z * hin[g];
    hout[g] = h;
    if (hh) split_bf16(h, hh + g, hl + g);
    float a = fmaxf(h, 0.f);
    act[g] = a;
    if (ah) split_bf16(a, ah + g, al + g);

    float p0 = a * v0[f];
    float p1 = a * v1[f];
    float p2 = v2 ? a * v2[f] : 0.f;
    float p3 = v3 ? a * v3[f] : 0.f;
#pragma unroll
    for (int o = 16; o; o >>= 1) {
        p0 += __shfl_down_sync(0xffffffffu, p0, o);
        p1 += __shfl_down_sync(0xffffffffu, p1, o);
        p2 += __shfl_down_sync(0xffffffffu, p2, o);
        p3 += __shfl_down_sync(0xffffffffu, p3, o);
    }
    const int lw = f >> 5, ll = f & 31;
    if (ll == 0) { sred[0][lw] = p0; sred[1][lw] = p1; sred[2][lw] = p2; sred[3][lw] = p3; }
    __syncthreads();
    if (f < 4) {
        float s = 0.f;
#pragma unroll
        for (int wdx = 0; wdx < 8; wdx++) s += sred[f][wdx];
        if      (f == 0) y0[m] = s;
        else if (f == 1) y1[m] = s;
        else if (f == 2) { if (y2) y2[m] = s; }
        else             { if (y3) y3[m] = s; }
    }
}

// ---------------------------------------------------------------------------
// Flat GRU gate (final mol step)
// ---------------------------------------------------------------------------
__global__ void fp_gru_gate(const float* __restrict__ gi, const float* __restrict__ gh,
                            const float* __restrict__ hin, float* __restrict__ hout,
                            float* __restrict__ out, int M)
{
    int g = blockIdx.x * blockDim.x + threadIdx.x;
    if (g >= M * FD_) return;
    int m = g / FD_, f = g - m * FD_;
    const float* gim = gi + (size_t)m * GN_;
    const float* ghm = gh + (size_t)m * GN_;
    float r = sigm_(gim[f] + ghm[f]);
    float z = sigm_(gim[FD_ + f] + ghm[FD_ + f]);
    float n = tanhf(gim[2 * FD_ + f] + r * ghm[2 * FD_ + f]);
    float h = (1.f - z) * n + z * hin[g];
    hout[g] = h;
    out[g] = fmaxf(h, 0.f);
}

// ---------------------------------------------------------------------------
// molecule feature init
// ---------------------------------------------------------------------------
__global__ void fp_molfeat(const float* __restrict__ act, const float* __restrict__ amask,
                           float* __restrict__ mf, __nv_bfloat16* __restrict__ mfh,
                           __nv_bfloat16* __restrict__ mfl, float* __restrict__ am)
{
    int b = blockIdx.x, f = threadIdx.x;
    float acc = 0.f;
    for (int l = 0; l < L_; l++)
        acc += act[((size_t)b * L_ + l) * FD_ + f] * amask[b * L_ + l];
    mf[b * FD_ + f] = acc;
    split_bf16(acc, mfh + b * FD_ + f, mfl + b * FD_ + f);
    am[b * FD_ + f] = fmaxf(acc, 0.f);
}

// ---------------------------------------------------------------------------
// Fused (optional GRU gate) + mol score + softmax + context, per-molecule.
// ---------------------------------------------------------------------------
__global__ __launch_bounds__(128)
void fp_molstep(const float* __restrict__ gi, const float* __restrict__ gh,
                float* __restrict__ mf, __nv_bfloat16* __restrict__ mfh,
                __nv_bfloat16* __restrict__ mfl, const float* __restrict__ am_g,
                float* __restrict__ outp,
                const float* __restrict__ maw, const float* __restrict__ mab,
                const float* __restrict__ actdot, const float* __restrict__ amask,
                const float* __restrict__ actT,
                __nv_bfloat16* __restrict__ ctxh, __nv_bfloat16* __restrict__ ctxl, int task)
{
    __shared__ float red[128];
    __shared__ float sam[256];
    __shared__ float sw[128];
    int b = blockIdx.x, t = threadIdx.x;

    if (gi) {
        const float* gim = gi + (size_t)b * GN_;
        const float* ghm = gh + (size_t)b * GN_;
#pragma unroll
        for (int ff = 0; ff < 2; ff++) {
            int f = t + ff * 128;
            size_t g = (size_t)b * FD_ + f;
            float r = sigm_(gim[f] + ghm[f]);
            float z = sigm_(gim[FD_ + f] + ghm[FD_ + f]);
            float n = tanhf(gim[2 * FD_ + f] + r * ghm[2 * FD_ + f]);
            float h = (1.f - z) * n + z * mf[g];
            mf[g] = h;
            split_bf16(h, mfh + g, mfl + g);
            float a = fmaxf(h, 0.f);
            sam[f] = a;
            if (outp) outp[g] = a;
        }
    } else {
        sam[t] = am_g[(size_t)b * FD_ + t];
        sam[t + 128] = am_g[(size_t)b * FD_ + t + 128];
    }
    __syncthreads();

    const float* ms = maw + task * 2 * FD_;
    float p = sam[t] * ms[t] + sam[t + 128] * ms[128 + t];
    red[t] = p; __syncthreads();
    for (int st = 64; st; st >>= 1) { if (t < st) red[t] += red[t + st]; __syncthreads(); }
    float sdv = red[0]; __syncthreads();
    float amv = amask[b * L_ + t];
    float s = lrelu_(sdv + actdot[task * BL_ + b * L_ + t] + mab[task]);
    if (amv == 0.f) s += NEG_;
    red[t] = s; __syncthreads();
    for (int st = 64; st; st >>= 1) { if (t < st) red[t] = fmaxf(red[t], red[t + st]); __syncthreads(); }
    float mx = red[0]; __syncthreads();
    float e = expf(s - mx);
    red[t] = e; __syncthreads();
    for (int st = 64; st; st >>= 1) { if (t < st) red[t] += red[t + st]; __syncthreads(); }
    float sum = red[0];
    sw[t] = e / sum * amv;
    __syncthreads();
    float a0 = 0.f, a1 = 0.f;
    for (int l = 0; l < L_; l++) {
        float wv = sw[l];
        const float* row = actT + ((size_t)b * L_ + l) * FD_;
        a0 += wv * row[t];
        a1 += wv * row[t + 128];
    }
    a0 = elu_(a0); a1 = elu_(a1);
    split_bf16(a0, ctxh + b * FD_ + t, ctxl + b * FD_ + t);
    split_bf16(a1, ctxh + b * FD_ + 128 + t, ctxl + b * FD_ + 128 + t);
}

// ---------------------------------------------------------------------------
// Host launch sequence
// ---------------------------------------------------------------------------
extern "C" void kernel_launch(void* const* d_in, const int* in_sizes, int n_in,
                              void* d_out, int out_size)
{
    const float* atom_list = (const float*)d_in[0];
    const float* bond_list = (const float*)d_in[1];
    const int*   adeg      = (const int*)d_in[2];
    const int*   bdeg      = (const int*)d_in[3];
    const float* amask     = (const float*)d_in[4];
    const float* atom_fc_w = (const float*)d_in[5];
    const float* atom_fc_b = (const float*)d_in[6];
    const float* nbr_fc_w  = (const float*)d_in[7];
    const float* nbr_fc_b  = (const float*)d_in[8];
    const float* align_w   = (const float*)d_in[9];
    const float* align_b   = (const float*)d_in[10];
    const float* attend_w  = (const float*)d_in[11];
    const float* attend_b  = (const float*)d_in[12];
    const float* gru_wih   = (const float*)d_in[13];
    const float* gru_whh   = (const float*)d_in[14];
    const float* gru_bih   = (const float*)d_in[15];
    const float* gru_bhh   = (const float*)d_in[16];
    const float* mgru_wih  = (const float*)d_in[17];
    const float* mgru_whh  = (const float*)d_in[18];
    const float* mgru_bih  = (const float*)d_in[19];
    const float* mgru_bhh  = (const float*)d_in[20];
    const float* mal_w     = (const float*)d_in[21];
    const float* mal_b     = (const float*)d_in[22];
    const float* mat_w     = (const float*)d_in[23];
    const float* mat_b     = (const float*)d_in[24];
    float* out = (float*)d_out;

    cudaFuncSetAttribute((const void*)tgemm<0>, cudaFuncAttributeMaxDynamicSharedMemorySize, SM_TOTAL);
    cudaFuncSetAttribute((const void*)tgemm<2>, cudaFuncAttributeMaxDynamicSharedMemorySize, SM_TOTAL);

#define SYM(p, s) cudaGetSymbolAddress((void**)&p, s)
    float *p_af, *p_h, *p_act, *p_actT, *p_gi, *p_gh, *p_sd, *p_nd,
          *p_ws, *p_ad, *p_mf, *p_am, *p_mgi, *p_mgh;
    __nv_bfloat16 *p_afh, *p_afl, *p_wfh, *p_wfl, *p_cxh, *p_cxl, *p_hh, *p_hl,
                  *p_ach, *p_acl, *p_mch, *p_mcl, *p_mfh, *p_mfl,
                  *w_atth, *w_attl, *w_ihh, *w_ihl, *w_hhh, *w_hhl,
                  *w_math, *w_matl, *w_mihh, *w_mihl, *w_mhhh, *w_mhhl;
    SYM(p_af, g_atomfeat); SYM(p_h, g_h); SYM(p_act, g_act);
    SYM(p_actT, g_actT); SYM(p_gi, g_gi); SYM(p_gh, g_gh);
    SYM(p_sd, g_sd); SYM(p_nd, g_nd); SYM(p_ws, g_wsum);
    SYM(p_ad, g_actdot); SYM(p_mf, g_molfeat); SYM(p_am, g_actmol);
    SYM(p_mgi, g_mgi); SYM(p_mgh, g_mgh);
    SYM(p_afh, g_af_h); SYM(p_afl, g_af_l); SYM(p_wfh, g_wf_h); SYM(p_wfl, g_wf_l);
    SYM(p_cxh, g_ctx_h); SYM(p_cxl, g_ctx_l); SYM(p_hh, g_h_h); SYM(p_hl, g_h_l);
    SYM(p_ach, g_act_h); SYM(p_acl, g_act_l); SYM(p_mch, g_mctx_h); SYM(p_mcl, g_mctx_l);
    SYM(p_mfh, g_mf_h); SYM(p_mfl, g_mf_l);
    SYM(w_atth, g_watt_h); SYM(w_attl, g_watt_l); SYM(w_ihh, g_wih_h); SYM(w_ihl, g_wih_l);
    SYM(w_hhh, g_whh_h); SYM(w_hhl, g_whh_l); SYM(w_math, g_mat_h); SYM(w_matl, g_mat_l);
    SYM(w_mihh, g_mih_h); SYM(w_mihl, g_mih_l); SYM(w_mhhh, g_mhh_h); SYM(w_mhhl, g_mhh_l);
#undef SYM

    fp_cvt_all<<<(CV6 + 255) / 256, 256>>>(attend_w, gru_wih, gru_whh, mat_w, mgru_wih, mgru_whh,
                                           w_atth, w_attl, w_ihh, w_ihl, w_hhh, w_hhl,
                                           w_math, w_matl, w_mihh, w_mihl, w_mhhh, w_mhhl);

    fp_atom_fc<<<BL_ / 16, 256>>>(atom_list, atom_fc_w, atom_fc_b, align_w,
                                  p_af, p_afh, p_afl, p_sd);
    fp_nbr_attn0<<<BL_ / 16, 256>>>(atom_list, bond_list, adeg, bdeg,
                                    nbr_fc_w, nbr_fc_b, align_w + 256,
                                    p_sd, align_b, p_wfh, p_wfl, p_ws);

    const dim3 gctx(FD_ / 64, BL_ / 128, 1);      // 16384 x 256
    const dim3 ggru(GN_ / 64, BL_ / 128, 2);      // 16384 x 768, batched gi/gh
    const dim3 gmol(GN_ / 64, 1, 2);              // 128 x 768, batched gi/gh

    // --- radius loop ---
    for (int r = 0; r < RADIUS_; r++) {
        const __nv_bfloat16* hprev_h = (r == 0) ? p_afh : p_hh;
        const __nv_bfloat16* hprev_l = (r == 0) ? p_afl : p_hl;
        const float* hprev_f = (r == 0) ? p_af : p_h;

        if (r > 0) {
            fp_attn<<<BL_ / 2, 256>>>(p_sd, p_nd, adeg, align_b + r, p_act,
                                      p_wfh, p_wfl, p_ws);
        }
        tgemm<2><<<gctx, 256, SM_TOTAL>>>(p_wfh, p_wfl, nullptr, nullptr,
                                          w_atth + (size_t)r * FD_ * FD_, w_attl + (size_t)r * FD_ * FD_,
                                          nullptr, nullptr,
                                          attend_b + r * FD_, nullptr, p_ws,
                                          nullptr, nullptr, p_cxh, p_cxl, FD_);
        tgemm<0><<<ggru, 256, SM_TOTAL>>>(p_cxh, p_cxl, hprev_h, hprev_l,
                                          w_ihh + (size_t)r * GN_ * FD_, w_ihl + (size_t)r * GN_ * FD_,
                                          w_hhh + (size_t)r * GN_ * FD_, w_hhl + (size_t)r * GN_ * FD_,
                                          gru_bih + r * GN_, gru_bhh + r * GN_, nullptr,
                                          p_gi, p_gh, nullptr, nullptr, GN_);
        bool last = (r == RADIUS_ - 1);
        if (!last) {
            fp_gru_gate_dot<<<BL_, 256>>>(p_gi, p_gh, hprev_f, p_h, p_hh, p_hl,
                                          p_act, nullptr, nullptr,
                                          align_w + (r + 1) * 512, align_w + (r + 1) * 512 + 256,
                                          nullptr, nullptr,
                                          p_sd, p_nd, nullptr, nullptr);
        } else {
            fp_gru_gate_dot<<<BL_, 256>>>(p_gi, p_gh, hprev_f, p_h, p_hh, p_hl,
                                          p_act, p_ach, p_acl,
                                          mal_w + 256, mal_w + 512 + 256,
                                          mal_w + 1024 + 256, mal_w + 1536 + 256,
                                          p_ad, p_ad + BL_, p_ad + 2 * BL_, p_ad + 3 * BL_);
        }
    }

    // --- molecule phase ---
    fp_molfeat<<<B_, FD_>>>(p_act, amask, p_mf, p_mfh, p_mfl, p_am);
    tgemm<0><<<gctx, 256, SM_TOTAL>>>(p_ach, p_acl, nullptr, nullptr,
                                      w_math, w_matl, nullptr, nullptr,
                                      mat_b, nullptr, nullptr,
                                      p_actT, nullptr, nullptr, nullptr, FD_);

    for (int it = 0; it < TASKS_ * T_; it++) {
        int task = it >> 1;
        const float* gi_arg = (it == 0) ? nullptr : p_mgi;
        float* outp = (it > 0 && ((it - 1) & 1)) ? out + (size_t)((it - 1) >> 1) * B_ * FD_
                                                 : nullptr;
        fp_molstep<<<B_, 128>>>(gi_arg, p_mgh, p_mf, p_mfh, p_mfl, p_am, outp,
                                mal_w, mal_b, p_ad, amask, p_actT, p_mch, p_mcl, task);
        tgemm<0><<<gmol, 256, SM_TOTAL>>>(p_mch, p_mcl, p_mfh, p_mfl,
                                          w_mihh, w_mihl, w_mhhh, w_mhhl,
                                          mgru_bih, mgru_bhh, nullptr,
                                          p_mgi, p_mgh, nullptr, nullptr, GN_);
    }
    fp_gru_gate<<<B_ * FD_ / 256, 256>>>(p_mgi, p_mgh, p_mf, p_mf,
                                         out + (size_t)(TASKS_ - 1) * B_ * FD_, B_);
}

// round 13
// speedup vs baseline: 1.0812x; 1.0106x over previous
#include <cuda_runtime.h>
#include <cuda_bf16.h>
#include <math.h>
#include <stdint.h>

// ---------------------------------------------------------------------------
// Problem constants
// ---------------------------------------------------------------------------
namespace {
constexpr int B_ = 128, L_ = 128, D_ = 6, FD_ = 256;
constexpr int IN_ATOM_ = 39, IN_BOND_ = 10, NBONDS_ = 256;
constexpr int RADIUS_ = 3, TASKS_ = 4, T_ = 2;
constexpr int BL_ = B_ * L_;        // 16384
constexpr float NEG_ = -9e8f;
constexpr int GN_ = 3 * FD_;        // 768
}

// ---------------------------------------------------------------------------
// Scratch buffers (device globals; no allocations allowed)
// ---------------------------------------------------------------------------
__device__ float g_atomfeat[BL_ * FD_];
__device__ float g_h       [BL_ * FD_];
__device__ float g_act     [BL_ * FD_];
__device__ float g_actT    [BL_ * FD_];
__device__ float g_gi      [BL_ * GN_];
__device__ float g_gh      [BL_ * GN_];
__device__ float g_sd      [BL_];
__device__ float g_nd      [BL_];
__device__ float g_wsum    [BL_];
__device__ float g_actdot  [TASKS_ * BL_];
__device__ float g_molfeat [B_ * FD_];
__device__ float g_actmol  [B_ * FD_];
__device__ float g_mgi     [B_ * GN_];
__device__ float g_mgh     [B_ * GN_];

// bf16 hi/lo activation buffers (16B aligned for uint4 / cp.async staging)
__device__ __align__(16) __nv_bfloat16 g_af_h [BL_ * FD_];
__device__ __align__(16) __nv_bfloat16 g_af_l [BL_ * FD_];
__device__ __align__(16) __nv_bfloat16 g_wf_h [BL_ * FD_];
__device__ __align__(16) __nv_bfloat16 g_wf_l [BL_ * FD_];
__device__ __align__(16) __nv_bfloat16 g_ctx_h[BL_ * FD_];
__device__ __align__(16) __nv_bfloat16 g_ctx_l[BL_ * FD_];
__device__ __align__(16) __nv_bfloat16 g_h_h  [BL_ * FD_];
__device__ __align__(16) __nv_bfloat16 g_h_l  [BL_ * FD_];
__device__ __align__(16) __nv_bfloat16 g_act_h[BL_ * FD_];
__device__ __align__(16) __nv_bfloat16 g_act_l[BL_ * FD_];
__device__ __align__(16) __nv_bfloat16 g_mctx_h[B_ * FD_];
__device__ __align__(16) __nv_bfloat16 g_mctx_l[B_ * FD_];
__device__ __align__(16) __nv_bfloat16 g_mf_h [B_ * FD_];
__device__ __align__(16) __nv_bfloat16 g_mf_l [B_ * FD_];
// bf16 hi/lo weights
__device__ __align__(16) __nv_bfloat16 g_watt_h[RADIUS_ * FD_ * FD_];
__device__ __align__(16) __nv_bfloat16 g_watt_l[RADIUS_ * FD_ * FD_];
__device__ __align__(16) __nv_bfloat16 g_wih_h [RADIUS_ * GN_ * FD_];
__device__ __align__(16) __nv_bfloat16 g_wih_l [RADIUS_ * GN_ * FD_];
__device__ __align__(16) __nv_bfloat16 g_whh_h [RADIUS_ * GN_ * FD_];
__device__ __align__(16) __nv_bfloat16 g_whh_l [RADIUS_ * GN_ * FD_];
__device__ __align__(16) __nv_bfloat16 g_mat_h [FD_ * FD_];
__device__ __align__(16) __nv_bfloat16 g_mat_l [FD_ * FD_];
__device__ __align__(16) __nv_bfloat16 g_mih_h [GN_ * FD_];
__device__ __align__(16) __nv_bfloat16 g_mih_l [GN_ * FD_];
__device__ __align__(16) __nv_bfloat16 g_mhh_h [GN_ * FD_];
__device__ __align__(16) __nv_bfloat16 g_mhh_l [GN_ * FD_];

__device__ __forceinline__ float lrelu_(float x) { return x > 0.f ? x : 0.01f * x; }
__device__ __forceinline__ float elu_(float x)   { return x > 0.f ? x : expm1f(x); }
__device__ __forceinline__ float sigm_(float x)  { return 1.f / (1.f + expf(-x)); }

__device__ __forceinline__ void split_bf16(float v, __nv_bfloat16* hp, __nv_bfloat16* lp) {
    __nv_bfloat16 h = __float2bfloat16(v);
    *hp = h;
    *lp = __float2bfloat16(v - __bfloat162float(h));
}

// ---------------------------------------------------------------------------
// mma.sync + ldmatrix + cp.async helpers (baseline PTX, compute_103-safe)
// ---------------------------------------------------------------------------
__device__ __forceinline__ uint32_t smem_u32_(const void* p) {
    uint32_t a;
    asm("{ .reg .u64 t; cvta.to.shared.u64 t, %1; cvt.u32.u64 %0, t; }" : "=r"(a) : "l"(p));
    return a;
}
__device__ __forceinline__ void ldm_x4_(uint32_t* r, uint32_t addr) {
    asm volatile("ldmatrix.sync.aligned.m8n8.x4.shared.b16 {%0,%1,%2,%3}, [%4];"
                 : "=r"(r[0]), "=r"(r[1]), "=r"(r[2]), "=r"(r[3]) : "r"(addr));
}
__device__ __forceinline__ void mma_(float* d, const uint32_t* a, uint32_t b0, uint32_t b1) {
    asm volatile(
        "mma.sync.aligned.m16n8k16.row.col.f32.bf16.bf16.f32 "
        "{%0,%1,%2,%3}, {%4,%5,%6,%7}, {%8,%9}, {%0,%1,%2,%3};"
        : "+f"(d[0]), "+f"(d[1]), "+f"(d[2]), "+f"(d[3])
        : "r"(a[0]), "r"(a[1]), "r"(a[2]), "r"(a[3]), "r"(b0), "r"(b1));
}
__device__ __forceinline__ void cp16_(uint32_t dst, const void* src) {
    asm volatile("cp.async.cg.shared.global [%0], [%1], 16;" :: "r"(dst), "l"(src));
}

// ---------------------------------------------------------------------------
// Pipelined HMMA GEMM: C = (Ahi+Alo) @ (Whi+Wlo)^T (bf16x3 emulation)
// CTA: 256 thr / 8 warps (4x2 grid), tile 128x64, warp tile 32x32.
// K chunks of 32, 2-stage cp.async pipeline, stride 40 bf16 (80 B rows).
// smem: 2 x 30,720 = 61,440 B -> 3 CTA/SM (24 warps/SM).
// EPI 0: Cf = acc + bias[n]  (fp32)
// EPI 2: elu(acc + rs[m]*bias[n]) -> Chi/Clo bf16 split
// gridDim.z==2 selects second (A2/W2/bias2/C2f) problem.
// ---------------------------------------------------------------------------
namespace {
constexpr int SMS_ = 40;                       // bf16 row stride (80 B)
constexpr int ST_AH = 0;
constexpr int ST_AL = 128 * SMS_ * 2;          // 10240
constexpr int ST_WH = 2 * 128 * SMS_ * 2;      // 20480
constexpr int ST_WL = ST_WH + 64 * SMS_ * 2;   // 25600
constexpr int STAGE_ = ST_WL + 64 * SMS_ * 2;  // 30720
constexpr int SM_TOTAL = 2 * STAGE_;           // 61440
}

template <int EPI>
__global__ __launch_bounds__(256, 3)
void tgemm(const __nv_bfloat16* __restrict__ Ahi, const __nv_bfloat16* __restrict__ Alo,
           const __nv_bfloat16* __restrict__ A2hi, const __nv_bfloat16* __restrict__ A2lo,
           const __nv_bfloat16* __restrict__ Whi, const __nv_bfloat16* __restrict__ Wlo,
           const __nv_bfloat16* __restrict__ W2hi, const __nv_bfloat16* __restrict__ W2lo,
           const float* __restrict__ bias, const float* __restrict__ bias2,
           const float* __restrict__ rs,
           float* __restrict__ Cf, float* __restrict__ C2f,
           __nv_bfloat16* __restrict__ Chi, __nv_bfloat16* __restrict__ Clo,
           int N)
{
    extern __shared__ char sm[];
    const uint32_t smb = smem_u32_(sm);
    const int tid = threadIdx.x, wid = tid >> 5, lane = tid & 31;
    if (blockIdx.z) { Ahi = A2hi; Alo = A2lo; Whi = W2hi; Wlo = W2lo; bias = bias2; Cf = C2f; }
    const int bm = blockIdx.y * 128, bn = blockIdx.x * 64;
    constexpr int K = 256;
    const int warp_m = wid >> 1, warp_n = wid & 1;   // 4x2 warp grid, warp tile 32x32

    auto stage = [&](int kc, int s) {
        const int koff = kc * 32;
        const uint32_t base = smb + s * STAGE_;
        for (int i = tid; i < 512; i += 256) {           // A: 128 rows x 4x16B
            int r = i >> 2, cb = (i & 3) << 4;
            uint32_t dst = (uint32_t)(r * 80 + cb);
            size_t g = (size_t)(bm + r) * K + koff + (cb >> 1);
            cp16_(base + ST_AH + dst, Ahi + g);
            cp16_(base + ST_AL + dst, Alo + g);
        }
        for (int i = tid; i < 256; i += 256) {           // W: 64 rows
            int r = i >> 2, cb = (i & 3) << 4;
            uint32_t dst = (uint32_t)(r * 80 + cb);
            size_t g = (size_t)(bn + r) * K + koff + (cb >> 1);
            cp16_(base + ST_WH + dst, Whi + g);
            cp16_(base + ST_WL + dst, Wlo + g);
        }
        asm volatile("cp.async.commit_group;");
    };

    stage(0, 0);
    stage(1, 1);

    float acc[2][4][4] = {};
    const int lrow = lane & 15;
    const int lcol = (lane >> 4) << 3;

#pragma unroll
    for (int kc = 0; kc < 8; kc++) {
        if (kc == 7) asm volatile("cp.async.wait_group 0;");
        else         asm volatile("cp.async.wait_group 1;");
        __syncthreads();
        const uint32_t sb = smb + (kc & 1) * STAGE_;
#pragma unroll
        for (int ks = 0; ks < 2; ks++) {
            const int k0 = ks * 16;
            uint32_t ah[2][4], al[2][4], bh[2][4], bl[2][4];
#pragma unroll
            for (int i = 0; i < 2; i++) {
                uint32_t off = (uint32_t)((warp_m * 32 + i * 16 + lrow) * SMS_ + k0 + lcol) * 2;
                ldm_x4_(ah[i], sb + ST_AH + off);
                ldm_x4_(al[i], sb + ST_AL + off);
            }
#pragma unroll
            for (int j2 = 0; j2 < 2; j2++) {
                uint32_t off = (uint32_t)((warp_n * 32 + j2 * 16 + lrow) * SMS_ + k0 + lcol) * 2;
                ldm_x4_(bh[j2], sb + ST_WH + off);
                ldm_x4_(bl[j2], sb + ST_WL + off);
            }
#pragma unroll
            for (int i = 0; i < 2; i++) {
#pragma unroll
                for (int j2 = 0; j2 < 2; j2++) {
#pragma unroll
                    for (int s = 0; s < 2; s++) {
                        float* d = acc[i][j2 * 2 + s];
                        mma_(d, ah[i], bh[j2][s], bh[j2][s + 2]);   // hi*hi
                        mma_(d, ah[i], bl[j2][s], bl[j2][s + 2]);   // hi*lo
                        mma_(d, al[i], bh[j2][s], bh[j2][s + 2]);   // lo*hi
                    }
                }
            }
        }
        if (kc < 6) {
            __syncthreads();
            stage(kc + 2, kc & 1);
        }
    }

    const int er = lane >> 2, ec = (lane & 3) << 1;
#pragma unroll
    for (int i = 0; i < 2; i++) {
        int m0 = bm + warp_m * 32 + i * 16 + er;
#pragma unroll
        for (int j = 0; j < 4; j++) {
            int n0 = bn + warp_n * 32 + j * 8 + ec;
            float b0 = bias[n0], b1 = bias[n0 + 1];
            if (EPI == 0) {
#pragma unroll
                for (int h = 0; h < 2; h++) {
                    int m = m0 + h * 8;
                    float2 o;
                    o.x = acc[i][j][2 * h + 0] + b0;
                    o.y = acc[i][j][2 * h + 1] + b1;
                    *(float2*)(Cf + (size_t)m * N + n0) = o;
                }
            } else {
#pragma unroll
                for (int h = 0; h < 2; h++) {
                    int m = m0 + h * 8;
                    float rsv = rs[m];
                    float v0 = elu_(acc[i][j][2 * h + 0] + rsv * b0);
                    float v1 = elu_(acc[i][j][2 * h + 1] + rsv * b1);
                    __nv_bfloat16 h0, l0, h1, l1;
                    split_bf16(v0, &h0, &l0); split_bf16(v1, &h1, &l1);
                    *(__nv_bfloat162*)(Chi + (size_t)m * N + n0) = __nv_bfloat162{h0, h1};
                    *(__nv_bfloat162*)(Clo + (size_t)m * N + n0) = __nv_bfloat162{l0, l1};
                }
            }
        }
    }
}

// ---------------------------------------------------------------------------
// fp32 -> bf16 hi/lo conversion: ALL weights in one launch
// ---------------------------------------------------------------------------
namespace {
constexpr int CV1 = RADIUS_ * FD_ * FD_;
constexpr int CV2 = CV1 + RADIUS_ * GN_ * FD_;
constexpr int CV3 = CV2 + RADIUS_ * GN_ * FD_;
constexpr int CV4 = CV3 + FD_ * FD_;
constexpr int CV5 = CV4 + GN_ * FD_;
constexpr int CV6 = CV5 + GN_ * FD_;
}
__global__ void fp_cvt_all(const float* __restrict__ s1, const float* __restrict__ s2,
                           const float* __restrict__ s3, const float* __restrict__ s4,
                           const float* __restrict__ s5, const float* __restrict__ s6,
                           __nv_bfloat16* __restrict__ h1, __nv_bfloat16* __restrict__ l1,
                           __nv_bfloat16* __restrict__ h2, __nv_bfloat16* __restrict__ l2,
                           __nv_bfloat16* __restrict__ h3, __nv_bfloat16* __restrict__ l3,
                           __nv_bfloat16* __restrict__ h4, __nv_bfloat16* __restrict__ l4,
                           __nv_bfloat16* __restrict__ h5, __nv_bfloat16* __restrict__ l5,
                           __nv_bfloat16* __restrict__ h6, __nv_bfloat16* __restrict__ l6)
{
    int i = blockIdx.x * 256 + threadIdx.x;
    if (i >= CV6) return;
    const float* s; __nv_bfloat16 *h, *l; int o;
    if      (i < CV1) { s = s1; h = h1; l = l1; o = 0;   }
    else if (i < CV2) { s = s2; h = h2; l = l2; o = CV1; }
    else if (i < CV3) { s = s3; h = h3; l = l3; o = CV2; }
    else if (i < CV4) { s = s4; h = h4; l = l4; o = CV3; }
    else if (i < CV5) { s = s5; h = h5; l = l5; o = CV4; }
    else              { s = s6; h = h6; l = l6; o = CV5; }
    int j = i - o;
    split_bf16(s[j], h + j, l + j);
}

// ---------------------------------------------------------------------------
// atom_fc: lrelu(X @ W^T + b); fp32 + bf16 hi/lo + fused self-dot (align_w[0])
// ---------------------------------------------------------------------------
__global__ __launch_bounds__(256)
void fp_atom_fc(const float* __restrict__ X, const float* __restrict__ W,
                const float* __restrict__ bias, const float* __restrict__ vdot,
                float* __restrict__ C,
                __nv_bfloat16* __restrict__ Ch, __nv_bfloat16* __restrict__ Cl,
                float* __restrict__ sd)
{
    __shared__ float sin_[16][IN_ATOM_];
    __shared__ float sred[16][8];
    const int r0 = blockIdx.x * 16;
    for (int i = threadIdx.x; i < 16 * IN_ATOM_; i += 256)
        sin_[i / IN_ATOM_][i % IN_ATOM_] =
            X[(size_t)(r0 + i / IN_ATOM_) * IN_ATOM_ + i % IN_ATOM_];
    __syncthreads();
    const int f = threadIdx.x;
    float acc[16] = {};
    for (int k = 0; k < IN_ATOM_; k++) {
        float wv = __ldg(&W[f * IN_ATOM_ + k]);
#pragma unroll
        for (int r = 0; r < 16; r++) acc[r] += wv * sin_[r][k];
    }
    float bv = bias[f];
    float vw = __ldg(&vdot[f]);
    const int lw = threadIdx.x >> 5, ll = threadIdx.x & 31;
#pragma unroll
    for (int r = 0; r < 16; r++) {
        float v = lrelu_(acc[r] + bv);
        size_t o = (size_t)(r0 + r) * FD_ + f;
        C[o] = v;
        split_bf16(v, Ch + o, Cl + o);
        float p = v * vw;
#pragma unroll
        for (int oo = 16; oo; oo >>= 1) p += __shfl_down_sync(0xffffffffu, p, oo);
        if (ll == 0) sred[r][lw] = p;
    }
    __syncthreads();
    if (threadIdx.x < 16) {
        float s = 0.f;
#pragma unroll
        for (int wdx = 0; wdx < 8; wdx++) s += sred[threadIdx.x][wdx];
        sd[r0 + threadIdx.x] = s;
    }
}

// ---------------------------------------------------------------------------
// FUSED r=0: neighbor_fc + score + softmax + weighted sum.
// ---------------------------------------------------------------------------
__global__ __launch_bounds__(256)
void fp_nbr_attn0(const float* __restrict__ atom_list, const float* __restrict__ bond_list,
                  const int* __restrict__ adeg, const int* __restrict__ bdeg,
                  const float* __restrict__ W, const float* __restrict__ bias,
                  const float* __restrict__ vdot,
                  const float* __restrict__ sd, const float* __restrict__ ab_ptr,
                  __nv_bfloat16* __restrict__ wfh, __nv_bfloat16* __restrict__ wfl,
                  float* __restrict__ wsum)
{
    constexpr int KIN = IN_ATOM_ + IN_BOND_;           // 49
    __shared__ float sin_[16][D_][KIN + 1];
    __shared__ float sred[D_][8];
    __shared__ float swd[D_];
    const int a0 = blockIdx.x * 16;
    const int f = threadIdx.x;
    const int lw = f >> 5, ll = f & 31;

    for (int i = f; i < 16 * D_ * KIN; i += 256) {
        int a = i / (D_ * KIN);
        int rem = i - a * (D_ * KIN);
        int d = rem / KIN, k = rem - d * KIN;
        int m = a0 + a;
        int b = m / L_;
        int rid = m * D_ + d;
        float v;
        if (k < IN_ATOM_) v = atom_list[((size_t)b * L_ + adeg[rid]) * IN_ATOM_ + k];
        else              v = bond_list[((size_t)b * NBONDS_ + bdeg[rid]) * IN_BOND_ + (k - IN_ATOM_)];
        sin_[a][d][k] = v;
    }
    float wreg[KIN];
#pragma unroll
    for (int k = 0; k < KIN; k++) wreg[k] = __ldg(&W[f * KIN + k]);
    const float bv = bias[f];
    const float vw = __ldg(&vdot[f]);
    __syncthreads();

    for (int a = 0; a < 16; a++) {
        const int m = a0 + a;
        float v[D_];
#pragma unroll
        for (int d = 0; d < D_; d++) {
            float acc = bv;
#pragma unroll
            for (int k = 0; k < KIN; k++) acc += wreg[k] * sin_[a][d][k];
            v[d] = lrelu_(acc);
        }
#pragma unroll
        for (int d = 0; d < D_; d++) {
            float p = v[d] * vw;
#pragma unroll
            for (int o = 16; o; o >>= 1) p += __shfl_down_sync(0xffffffffu, p, o);
            if (ll == 0) sred[d][lw] = p;
        }
        __syncthreads();
        if (f == 0) {
            const float ab = ab_ptr[0];
            const float sdv = sd[m];
            float sc[D_], msk[D_];
            float mx = -3.4e38f;
#pragma unroll
            for (int d = 0; d < D_; d++) {
                float ndv = 0.f;
#pragma unroll
                for (int wdx = 0; wdx < 8; wdx++) ndv += sred[d][wdx];
                float s = lrelu_(sdv + ndv + ab);
                bool pad = (adeg[m * D_ + d] == L_ - 1);
                if (pad) s += NEG_;
                msk[d] = pad ? 0.f : 1.f;
                sc[d] = s;
                mx = fmaxf(mx, s);
            }
            float sum = 0.f;
#pragma unroll
            for (int d = 0; d < D_; d++) { float e = expf(sc[d] - mx); sum += e; sc[d] = e; }
            float inv = 1.f / sum, ws = 0.f;
#pragma unroll
            for (int d = 0; d < D_; d++) {
                float wv = sc[d] * inv * msk[d];
                swd[d] = wv;
                ws += wv;
            }
            wsum[m] = ws;
        }
        __syncthreads();
        float accw = 0.f;
#pragma unroll
        for (int d = 0; d < D_; d++) accw += swd[d] * v[d];
        split_bf16(accw, wfh + (size_t)m * FD_ + f, wfl + (size_t)m * FD_ + f);
    }
}

// ---------------------------------------------------------------------------
// FUSED attention for r>=1: score + softmax + weighted sum over act.
// ---------------------------------------------------------------------------
__global__ __launch_bounds__(256)
void fp_attn(const float* __restrict__ sd, const float* __restrict__ nd,
             const int* __restrict__ adeg, const float* __restrict__ ab_ptr,
             const float* __restrict__ src,
             __nv_bfloat16* __restrict__ wfh, __nv_bfloat16* __restrict__ wfl,
             float* __restrict__ wsum)
{
    __shared__ float sw[2][D_];
    __shared__ int sidx[2][D_];
    const int m0 = blockIdx.x * 2;

    if ((threadIdx.x & 127) == 0) {
        const int r = threadIdx.x >> 7;
        const int m = m0 + r;
        const int b = m / L_;
        const float ab = ab_ptr[0];
        const float sdv = sd[m];
        float sc[D_], msk[D_];
        int idxs[D_];
        float mx = -3.4e38f;
#pragma unroll
        for (int d = 0; d < D_; d++) {
            int idx = adeg[m * D_ + d];
            idxs[d] = idx;
            float ndv = nd[b * L_ + idx];
            float s = lrelu_(sdv + ndv + ab);
            bool pad = (idx == L_ - 1);
            if (pad) s += NEG_;
            msk[d] = pad ? 0.f : 1.f;
            sc[d] = s;
            mx = fmaxf(mx, s);
        }
        float sum = 0.f;
#pragma unroll
        for (int d = 0; d < D_; d++) { float e = expf(sc[d] - mx); sum += e; sc[d] = e; }
        float inv = 1.f / sum, ws = 0.f;
#pragma unroll
        for (int d = 0; d < D_; d++) {
            float wv = sc[d] * inv * msk[d];
            sw[r][d] = wv;
            sidx[r][d] = idxs[d];
            ws += wv;
        }
        wsum[m] = ws;
    }
    __syncthreads();

    const int f = threadIdx.x;
#pragma unroll
    for (int r = 0; r < 2; r++) {
        int m = m0 + r;
        int b = m / L_;
        float acc = 0.f;
#pragma unroll
        for (int d = 0; d < D_; d++)
            acc += sw[r][d] * src[(size_t)(b * L_ + sidx[r][d]) * FD_ + f];
        split_bf16(acc, wfh + (size_t)m * FD_ + f, wfl + (size_t)m * FD_ + f);
    }
}

// ---------------------------------------------------------------------------
// GRU gate + fused dot products on act (one block per row, 256 threads).
// ---------------------------------------------------------------------------
__global__ __launch_bounds__(256)
void fp_gru_gate_dot(const float* __restrict__ gi, const float* __restrict__ gh,
                     const float* __restrict__ hin, float* __restrict__ hout,
                     __nv_bfloat16* __restrict__ hh, __nv_bfloat16* __restrict__ hl,
                     float* __restrict__ act,
                     __nv_bfloat16* __restrict__ ah, __nv_bfloat16* __restrict__ al,
                     const float* __restrict__ v0, const float* __restrict__ v1,
                     const float* __restrict__ v2, const float* __restrict__ v3,
                     float* __restrict__ y0, float* __restrict__ y1,
                     float* __restrict__ y2, float* __restrict__ y3)
{
    __shared__ float sred[4][8];
    const int m = blockIdx.x, f = threadIdx.x;
    const size_t g = (size_t)m * FD_ + f;
    const float* gim = gi + (size_t)m * GN_;
    const float* ghm = gh + (size_t)m * GN_;
    float r = sigm_(gim[f] + ghm[f]);
    float z = sigm_(gim[FD_ + f] + ghm[FD_ + f]);
    float n = tanhf(gim[2 * FD_ + f] + r * ghm[2 * FD_ + f]);
    float h = (1.f - z) * n + z * hin[g];
    hout[g] = h;
    if (hh) split_bf16(h, hh + g, hl + g);
    float a = fmaxf(h, 0.f);
    act[g] = a;
    if (ah) split_bf16(a, ah + g, al + g);

    float p0 = a * v0[f];
    float p1 = a * v1[f];
    float p2 = v2 ? a * v2[f] : 0.f;
    float p3 = v3 ? a * v3[f] : 0.f;
#pragma unroll
    for (int o = 16; o; o >>= 1) {
        p0 += __shfl_down_sync(0xffffffffu, p0, o);
        p1 += __shfl_down_sync(0xffffffffu, p1, o);
        p2 += __shfl_down_sync(0xffffffffu, p2, o);
        p3 += __shfl_down_sync(0xffffffffu, p3, o);
    }
    const int lw = f >> 5, ll = f & 31;
    if (ll == 0) { sred[0][lw] = p0; sred[1][lw] = p1; sred[2][lw] = p2; sred[3][lw] = p3; }
    __syncthreads();
    if (f < 4) {
        float s = 0.f;
#pragma unroll
        for (int wdx = 0; wdx < 8; wdx++) s += sred[f][wdx];
        if      (f == 0) y0[m] = s;
        else if (f == 1) y1[m] = s;
        else if (f == 2) { if (y2) y2[m] = s; }
        else             { if (y3) y3[m] = s; }
    }
}

// ---------------------------------------------------------------------------
// Flat GRU gate (final mol step)
// ---------------------------------------------------------------------------
__global__ void fp_gru_gate(const float* __restrict__ gi, const float* __restrict__ gh,
                            const float* __restrict__ hin, float* __restrict__ hout,
                            float* __restrict__ out, int M)
{
    int g = blockIdx.x * blockDim.x + threadIdx.x;
    if (g >= M * FD_) return;
    int m = g / FD_, f = g - m * FD_;
    const float* gim = gi + (size_t)m * GN_;
    const float* ghm = gh + (size_t)m * GN_;
    float r = sigm_(gim[f] + ghm[f]);
    float z = sigm_(gim[FD_ + f] + ghm[FD_ + f]);
    float n = tanhf(gim[2 * FD_ + f] + r * ghm[2 * FD_ + f]);
    float h = (1.f - z) * n + z * hin[g];
    hout[g] = h;
    out[g] = fmaxf(h, 0.f);
}

// ---------------------------------------------------------------------------
// molecule feature init
// ---------------------------------------------------------------------------
__global__ void fp_molfeat(const float* __restrict__ act, const float* __restrict__ amask,
                           float* __restrict__ mf, __nv_bfloat16* __restrict__ mfh,
                           __nv_bfloat16* __restrict__ mfl, float* __restrict__ am)
{
    int b = blockIdx.x, f = threadIdx.x;
    float acc = 0.f;
    for (int l = 0; l < L_; l++)
        acc += act[((size_t)b * L_ + l) * FD_ + f] * amask[b * L_ + l];
    mf[b * FD_ + f] = acc;
    split_bf16(acc, mfh + b * FD_ + f, mfl + b * FD_ + f);
    am[b * FD_ + f] = fmaxf(acc, 0.f);
}

// ---------------------------------------------------------------------------
// Fused (optional GRU gate) + mol score + softmax + context, per-molecule.
// ---------------------------------------------------------------------------
__global__ __launch_bounds__(128)
void fp_molstep(const float* __restrict__ gi, const float* __restrict__ gh,
                float* __restrict__ mf, __nv_bfloat16* __restrict__ mfh,
                __nv_bfloat16* __restrict__ mfl, const float* __restrict__ am_g,
                float* __restrict__ outp,
                const float* __restrict__ maw, const float* __restrict__ mab,
                const float* __restrict__ actdot, const float* __restrict__ amask,
                const float* __restrict__ actT,
                __nv_bfloat16* __restrict__ ctxh, __nv_bfloat16* __restrict__ ctxl, int task)
{
    __shared__ float red[128];
    __shared__ float sam[256];
    __shared__ float sw[128];
    int b = blockIdx.x, t = threadIdx.x;

    if (gi) {
        const float* gim = gi + (size_t)b * GN_;
        const float* ghm = gh + (size_t)b * GN_;
#pragma unroll
        for (int ff = 0; ff < 2; ff++) {
            int f = t + ff * 128;
            size_t g = (size_t)b * FD_ + f;
            float r = sigm_(gim[f] + ghm[f]);
            float z = sigm_(gim[FD_ + f] + ghm[FD_ + f]);
            float n = tanhf(gim[2 * FD_ + f] + r * ghm[2 * FD_ + f]);
            float h = (1.f - z) * n + z * mf[g];
            mf[g] = h;
            split_bf16(h, mfh + g, mfl + g);
            float a = fmaxf(h, 0.f);
            sam[f] = a;
            if (outp) outp[g] = a;
        }
    } else {
        sam[t] = am_g[(size_t)b * FD_ + t];
        sam[t + 128] = am_g[(size_t)b * FD_ + t + 128];
    }
    __syncthreads();

    const float* ms = maw + task * 2 * FD_;
    float p = sam[t] * ms[t] + sam[t + 128] * ms[128 + t];
    red[t] = p; __syncthreads();
    for (int st = 64; st; st >>= 1) { if (t < st) red[t] += red[t + st]; __syncthreads(); }
    float sdv = red[0]; __syncthreads();
    float amv = amask[b * L_ + t];
    float s = lrelu_(sdv + actdot[task * BL_ + b * L_ + t] + mab[task]);
    if (amv == 0.f) s += NEG_;
    red[t] = s; __syncthreads();
    for (int st = 64; st; st >>= 1) { if (t < st) red[t] = fmaxf(red[t], red[t + st]); __syncthreads(); }
    float mx = red[0]; __syncthreads();
    float e = expf(s - mx);
    red[t] = e; __syncthreads();
    for (int st = 64; st; st >>= 1) { if (t < st) red[t] += red[t + st]; __syncthreads(); }
    float sum = red[0];
    sw[t] = e / sum * amv;
    __syncthreads();
    float a0 = 0.f, a1 = 0.f;
    for (int l = 0; l < L_; l++) {
        float wv = sw[l];
        const float* row = actT + ((size_t)b * L_ + l) * FD_;
        a0 += wv * row[t];
        a1 += wv * row[t + 128];
    }
    a0 = elu_(a0); a1 = elu_(a1);
    split_bf16(a0, ctxh + b * FD_ + t, ctxl + b * FD_ + t);
    split_bf16(a1, ctxh + b * FD_ + 128 + t, ctxl + b * FD_ + 128 + t);
}

// ---------------------------------------------------------------------------
// Host launch sequence
// ---------------------------------------------------------------------------
extern "C" void kernel_launch(void* const* d_in, const int* in_sizes, int n_in,
                              void* d_out, int out_size)
{
    const float* atom_list = (const float*)d_in[0];
    const float* bond_list = (const float*)d_in[1];
    const int*   adeg      = (const int*)d_in[2];
    const int*   bdeg      = (const int*)d_in[3];
    const float* amask     = (const float*)d_in[4];
    const float* atom_fc_w = (const float*)d_in[5];
    const float* atom_fc_b = (const float*)d_in[6];
    const float* nbr_fc_w  = (const float*)d_in[7];
    const float* nbr_fc_b  = (const float*)d_in[8];
    const float* align_w   = (const float*)d_in[9];
    const float* align_b   = (const float*)d_in[10];
    const float* attend_w  = (const float*)d_in[11];
    const float* attend_b  = (const float*)d_in[12];
    const float* gru_wih   = (const float*)d_in[13];
    const float* gru_whh   = (const float*)d_in[14];
    const float* gru_bih   = (const float*)d_in[15];
    const float* gru_bhh   = (const float*)d_in[16];
    const float* mgru_wih  = (const float*)d_in[17];
    const float* mgru_whh  = (const float*)d_in[18];
    const float* mgru_bih  = (const float*)d_in[19];
    const float* mgru_bhh  = (const float*)d_in[20];
    const float* mal_w     = (const float*)d_in[21];
    const float* mal_b     = (const float*)d_in[22];
    const float* mat_w     = (const float*)d_in[23];
    const float* mat_b     = (const float*)d_in[24];
    float* out = (float*)d_out;

    cudaFuncSetAttribute((const void*)tgemm<0>, cudaFuncAttributeMaxDynamicSharedMemorySize, SM_TOTAL);
    cudaFuncSetAttribute((const void*)tgemm<2>, cudaFuncAttributeMaxDynamicSharedMemorySize, SM_TOTAL);

#define SYM(p, s) cudaGetSymbolAddress((void**)&p, s)
    float *p_af, *p_h, *p_act, *p_actT, *p_gi, *p_gh, *p_sd, *p_nd,
          *p_ws, *p_ad, *p_mf, *p_am, *p_mgi, *p_mgh;
    __nv_bfloat16 *p_afh, *p_afl, *p_wfh, *p_wfl, *p_cxh, *p_cxl, *p_hh, *p_hl,
                  *p_ach, *p_acl, *p_mch, *p_mcl, *p_mfh, *p_mfl,
                  *w_atth, *w_attl, *w_ihh, *w_ihl, *w_hhh, *w_hhl,
                  *w_math, *w_matl, *w_mihh, *w_mihl, *w_mhhh, *w_mhhl;
    SYM(p_af, g_atomfeat); SYM(p_h, g_h); SYM(p_act, g_act);
    SYM(p_actT, g_actT); SYM(p_gi, g_gi); SYM(p_gh, g_gh);
    SYM(p_sd, g_sd); SYM(p_nd, g_nd); SYM(p_ws, g_wsum);
    SYM(p_ad, g_actdot); SYM(p_mf, g_molfeat); SYM(p_am, g_actmol);
    SYM(p_mgi, g_mgi); SYM(p_mgh, g_mgh);
    SYM(p_afh, g_af_h); SYM(p_afl, g_af_l); SYM(p_wfh, g_wf_h); SYM(p_wfl, g_wf_l);
    SYM(p_cxh, g_ctx_h); SYM(p_cxl, g_ctx_l); SYM(p_hh, g_h_h); SYM(p_hl, g_h_l);
    SYM(p_ach, g_act_h); SYM(p_acl, g_act_l); SYM(p_mch, g_mctx_h); SYM(p_mcl, g_mctx_l);
    SYM(p_mfh, g_mf_h); SYM(p_mfl, g_mf_l);
    SYM(w_atth, g_watt_h); SYM(w_attl, g_watt_l); SYM(w_ihh, g_wih_h); SYM(w_ihl, g_wih_l);
    SYM(w_hhh, g_whh_h); SYM(w_hhl, g_whh_l); SYM(w_math, g_mat_h); SYM(w_matl, g_mat_l);
    SYM(w_mihh, g_mih_h); SYM(w_mihl, g_mih_l); SYM(w_mhhh, g_mhh_h); SYM(w_mhhl, g_mhh_l);
#undef SYM

    fp_cvt_all<<<(CV6 + 255) / 256, 256>>>(attend_w, gru_wih, gru_whh, mat_w, mgru_wih, mgru_whh,
                                           w_atth, w_attl, w_ihh, w_ihl, w_hhh, w_hhl,
                                           w_math, w_matl, w_mihh, w_mihl, w_mhhh, w_mhhl);

    fp_atom_fc<<<BL_ / 16, 256>>>(atom_list, atom_fc_w, atom_fc_b, align_w,
                                  p_af, p_afh, p_afl, p_sd);
    fp_nbr_attn0<<<BL_ / 16, 256>>>(atom_list, bond_list, adeg, bdeg,
                                    nbr_fc_w, nbr_fc_b, align_w + 256,
                                    p_sd, align_b, p_wfh, p_wfl, p_ws);

    const dim3 gctx(FD_ / 64, BL_ / 128, 1);      // 16384 x 256
    const dim3 ggru(GN_ / 64, BL_ / 128, 2);      // 16384 x 768, batched gi/gh
    const dim3 gmol(GN_ / 64, 1, 2);              // 128 x 768, batched gi/gh

    // --- radius loop ---
    for (int r = 0; r < RADIUS_; r++) {
        const __nv_bfloat16* hprev_h = (r == 0) ? p_afh : p_hh;
        const __nv_bfloat16* hprev_l = (r == 0) ? p_afl : p_hl;
        const float* hprev_f = (r == 0) ? p_af : p_h;

        if (r > 0) {
            fp_attn<<<BL_ / 2, 256>>>(p_sd, p_nd, adeg, align_b + r, p_act,
                                      p_wfh, p_wfl, p_ws);
        }
        tgemm<2><<<gctx, 256, SM_TOTAL>>>(p_wfh, p_wfl, nullptr, nullptr,
                                          w_atth + (size_t)r * FD_ * FD_, w_attl + (size_t)r * FD_ * FD_,
                                          nullptr, nullptr,
                                          attend_b + r * FD_, nullptr, p_ws,
                                          nullptr, nullptr, p_cxh, p_cxl, FD_);
        tgemm<0><<<ggru, 256, SM_TOTAL>>>(p_cxh, p_cxl, hprev_h, hprev_l,
                                          w_ihh + (size_t)r * GN_ * FD_, w_ihl + (size_t)r * GN_ * FD_,
                                          w_hhh + (size_t)r * GN_ * FD_, w_hhl + (size_t)r * GN_ * FD_,
                                          gru_bih + r * GN_, gru_bhh + r * GN_, nullptr,
                                          p_gi, p_gh, nullptr, nullptr, GN_);
        bool last = (r == RADIUS_ - 1);
        if (!last) {
            fp_gru_gate_dot<<<BL_, 256>>>(p_gi, p_gh, hprev_f, p_h, p_hh, p_hl,
                                          p_act, nullptr, nullptr,
                                          align_w + (r + 1) * 512, align_w + (r + 1) * 512 + 256,
                                          nullptr, nullptr,
                                          p_sd, p_nd, nullptr, nullptr);
        } else {
            fp_gru_gate_dot<<<BL_, 256>>>(p_gi, p_gh, hprev_f, p_h, p_hh, p_hl,
                                          p_act, p_ach, p_acl,
                                          mal_w + 256, mal_w + 512 + 256,
                                          mal_w + 1024 + 256, mal_w + 1536 + 256,
                                          p_ad, p_ad + BL_, p_ad + 2 * BL_, p_ad + 3 * BL_);
        }
    }

    // --- molecule phase ---
    fp_molfeat<<<B_, FD_>>>(p_act, amask, p_mf, p_mfh, p_mfl, p_am);
    tgemm<0><<<gctx, 256, SM_TOTAL>>>(p_ach, p_acl, nullptr, nullptr,
                                      w_math, w_matl, nullptr, nullptr,
                                      mat_b, nullptr, nullptr,
                                      p_actT, nullptr, nullptr, nullptr, FD_);

    for (int it = 0; it < TASKS_ * T_; it++) {
        int task = it >> 1;
        const float* gi_arg = (it == 0) ? nullptr : p_mgi;
        float* outp = (it > 0 && ((it - 1) & 1)) ? out + (size_t)((it - 1) >> 1) * B_ * FD_
                                                 : nullptr;
        fp_molstep<<<B_, 128>>>(gi_arg, p_mgh, p_mf, p_mfh, p_mfl, p_am, outp,
                                mal_w, mal_b, p_ad, amask, p_actT, p_mch, p_mcl, task);
        tgemm<0><<<gmol, 256, SM_TOTAL>>>(p_mch, p_mcl, p_mfh, p_mfl,
                                          w_mihh, w_mihl, w_mhhh, w_mhhl,
                                          mgru_bih, mgru_bhh, nullptr,
                                          p_mgi, p_mgh, nullptr, nullptr, GN_);
    }
    fp_gru_gate<<<B_ * FD_ / 256, 256>>>(p_mgi, p_mgh, p_mf, p_mf,
                                         out + (size_t)(TASKS_ - 1) * B_ * FD_, B_);
}